// round 11
// baseline (speedup 1.0000x reference)
#include <cuda_runtime.h>
#include <cuda_fp16.h>
#include <math.h>
#include <stdint.h>

#define BBATCH 16
#define SSEQ   2048
#define EMB    768
#define NHEAD  8
#define DHEAD  96
#define MROWS  (BBATCH*SSEQ)   // 32768
#define KDIM   768
#define NCH1   12              // 768 / 64  (1-pass, BK=64)
#define NCH2   24              // 768 / 32  (2-pass, BK=32)

// ---------------- scratch (device globals; allocation-free rule) -----------
__device__ __half  g_qkvh[(size_t)MROWS*2304];   // fp16 qkv (150 MB)
__device__ __half  g_fhi[(size_t)MROWS*KDIM];
__device__ __half  g_chi[(size_t)MROWS*KDIM];
__device__ __half  g_ohi[(size_t)MROWS*KDIM];
__device__ __half  g_olo[(size_t)MROWS*KDIM];
__device__ float   g_part[(size_t)MROWS*12];
__device__ __half  g_whi[(size_t)(2304+768+384)*KDIM];

// ---------------- helpers ---------------------------------------------------
__device__ __forceinline__ uint32_t s2u(const void* p){
    uint32_t a;
    asm("{ .reg .u64 t; cvta.to.shared.u64 t, %1; cvt.u32.u64 %0, t; }":"=r"(a):"l"(p));
    return a;
}
#define SWZ(o)   ((o) ^ (((o) >> 3) & 0x70))
#define SWZ64(o) ((o) ^ (((o) >> 3) & 0x30))
#define CP16(s, g) asm volatile("cp.async.cg.shared.global [%0], [%1], 16;"::"r"(s),"l"(g):"memory")

__device__ __forceinline__ void mma16816(float* c, const uint32_t* a, uint32_t b0, uint32_t b1){
    asm volatile("mma.sync.aligned.m16n8k16.row.col.f32.f16.f16.f32 "
        "{%0,%1,%2,%3},{%4,%5,%6,%7},{%8,%9},{%0,%1,%2,%3};"
        : "+f"(c[0]), "+f"(c[1]), "+f"(c[2]), "+f"(c[3])
        : "r"(a[0]), "r"(a[1]), "r"(a[2]), "r"(a[3]), "r"(b0), "r"(b1));
}

__device__ __forceinline__ void split_one(float x, __half& h, __half& l){
    h = __float2half(x);
    l = __float2half(x - __half2float(h));
}

// ---------------- fp32 -> fp16 convert, vectorized x4 ----------------------
__global__ __launch_bounds__(256)
void conv4(const float* __restrict__ src, __half* __restrict__ hi, size_t n4){
    size_t i = (size_t)blockIdx.x * blockDim.x + threadIdx.x;
    if (i >= n4) return;
    float4 v = ((const float4*)src)[i];
    ((__half2*)hi)[2*i]   = __halves2half2(__float2half(v.x), __float2half(v.y));
    ((__half2*)hi)[2*i+1] = __halves2half2(__float2half(v.z), __float2half(v.w));
}

__global__ __launch_bounds__(256)
void conv4x2(const float* __restrict__ sa, __half* __restrict__ ha, size_t na4,
             const float* __restrict__ sb, __half* __restrict__ hb, size_t nb4){
    size_t i = (size_t)blockIdx.x * blockDim.x + threadIdx.x;
    const float* src; __half* hi;
    if (i < na4){ src = sa; hi = ha; }
    else if (i < na4 + nb4){ i -= na4; src = sb; hi = hb; }
    else return;
    float4 v = ((const float4*)src)[i];
    ((__half2*)hi)[2*i]   = __halves2half2(__float2half(v.x), __float2half(v.y));
    ((__half2*)hi)[2*i+1] = __halves2half2(__float2half(v.z), __float2half(v.w));
}

// ---------------- 1-pass GEMM: C = Ahi @ Bhi^T + bias, BK=64 ---------------
// CTA 128x128, 256 thr, occ 2, 3-stage ring.
// EPI: 2 = fp16 hi/lo planes out, 3 = fp16 (hi only) out.
template<int EPI>
__global__ __launch_bounds__(256, 2)
void gemm_1p(const __half* __restrict__ Ahi, const __half* __restrict__ Bhi,
             const float* __restrict__ bias,
             __half* __restrict__ Chi, __half* __restrict__ Clo, int N)
{
    extern __shared__ __align__(1024) char sm[];
    constexpr uint32_t STGB = 32768u;
    const int tid = threadIdx.x, lane = tid & 31, warp = tid >> 5;
    const int m0 = blockIdx.y * 128, n0 = blockIdx.x * 128;
    const int wm = (warp & 1) * 64, wn = (warp >> 1) * 32;
    const uint32_t sbase = s2u(sm);

    auto load_tile = [&](int t){
        const uint32_t st = sbase + (uint32_t)(t % 3) * STGB;
        const int k0 = t * 64;
        #pragma unroll
        for (int i = 0; i < 4; i++){
            int g = tid + i * 256;
            int row = g >> 3, gg = g & 7;
            uint32_t d = SWZ((uint32_t)(row * 128 + gg * 16));
            CP16(st + d, Ahi + (size_t)(m0 + row) * KDIM + k0 + gg * 8);
        }
        #pragma unroll
        for (int i = 0; i < 4; i++){
            int g = tid + i * 256;
            int row = g >> 3, gg = g & 7;
            uint32_t d = SWZ((uint32_t)(row * 128 + gg * 16));
            CP16(st + 16384u + d, Bhi + (size_t)(n0 + row) * KDIM + k0 + gg * 8);
        }
        asm volatile("cp.async.commit_group;" ::: "memory");
    };

    float acc[4][4][4];
    #pragma unroll
    for (int mi = 0; mi < 4; mi++)
        #pragma unroll
        for (int ni = 0; ni < 4; ni++)
            #pragma unroll
            for (int r = 0; r < 4; r++) acc[mi][ni][r] = 0.0f;

    load_tile(0);
    load_tile(1);

    const uint32_t aRow = (uint32_t)(lane & 15);
    const uint32_t aCol = (uint32_t)(lane >> 4) * 16u;
    const uint32_t bRow = (uint32_t)(((lane >> 4) & 1) * 8 + (lane & 7));
    const uint32_t bCol = (uint32_t)((lane >> 3) & 1) * 16u;

    #pragma unroll 1
    for (int t = 0; t < NCH1; t++){
        if (t < NCH1 - 1) asm volatile("cp.async.wait_group 1;" ::: "memory");
        else              asm volatile("cp.async.wait_group 0;" ::: "memory");
        __syncthreads();
        if (t + 2 < NCH1) load_tile(t + 2);

        const uint32_t sA = sbase + (uint32_t)(t % 3) * STGB;
        const uint32_t sB = sA + 16384u;

        #pragma unroll
        for (int kk = 0; kk < 4; kk++){
            const uint32_t kb = (uint32_t)kk * 32u;
            uint32_t a[4][4], bh[8];
            #pragma unroll
            for (int np = 0; np < 2; np++){
                uint32_t ad = sB + SWZ((uint32_t)((wn + np*16 + bRow) * 128) + kb + bCol);
                asm volatile("ldmatrix.sync.aligned.m8n8.x4.shared.b16 {%0,%1,%2,%3},[%4];"
                    : "=r"(bh[np*4]), "=r"(bh[np*4+1]), "=r"(bh[np*4+2]), "=r"(bh[np*4+3]) : "r"(ad));
            }
            #pragma unroll
            for (int mi = 0; mi < 4; mi++){
                uint32_t ad = sA + SWZ((uint32_t)((wm + mi*16 + aRow) * 128) + kb + aCol);
                asm volatile("ldmatrix.sync.aligned.m8n8.x4.shared.b16 {%0,%1,%2,%3},[%4];"
                    : "=r"(a[mi][0]), "=r"(a[mi][1]), "=r"(a[mi][2]), "=r"(a[mi][3]) : "r"(ad));
            }
            #pragma unroll
            for (int mi = 0; mi < 4; mi++)
                #pragma unroll
                for (int ni = 0; ni < 4; ni++)
                    mma16816(acc[mi][ni], a[mi], bh[(ni>>1)*4 + (ni&1)*2], bh[(ni>>1)*4 + (ni&1)*2 + 1]);
        }
    }

    const int erow = lane >> 2;
    const int ecol = (lane & 3) * 2;
    #pragma unroll
    for (int mi = 0; mi < 4; mi++){
        #pragma unroll
        for (int ni = 0; ni < 4; ni++){
            const int row = m0 + wm + mi * 16 + erow;
            const int col = n0 + wn + ni * 8 + ecol;
            const float b0 = bias[col], b1 = bias[col + 1];
            float v0 = acc[mi][ni][0] + b0, v1 = acc[mi][ni][1] + b1;
            float v2 = acc[mi][ni][2] + b0, v3 = acc[mi][ni][3] + b1;
            if (EPI == 2){
                __half h0,h1,h2,h3,l0,l1,l2,l3;
                split_one(v0,h0,l0); split_one(v1,h1,l1);
                split_one(v2,h2,l2); split_one(v3,h3,l3);
                *(__half2*)(Chi + (size_t)row * N + col)       = __halves2half2(h0, h1);
                *(__half2*)(Clo + (size_t)row * N + col)       = __halves2half2(l0, l1);
                *(__half2*)(Chi + (size_t)(row + 8) * N + col) = __halves2half2(h2, h3);
                *(__half2*)(Clo + (size_t)(row + 8) * N + col) = __halves2half2(l2, l3);
            } else {
                *(__half2*)(Chi + (size_t)row * N + col)
                    = __halves2half2(__float2half(v0), __float2half(v1));
                *(__half2*)(Chi + (size_t)(row + 8) * N + col)
                    = __halves2half2(__float2half(v2), __float2half(v3));
            }
        }
    }
}

// ---------------- gemm3 fused: h=relu((Ahi+Alo)@W1^T+b1); partial dot w2 ----
__global__ __launch_bounds__(256, 2)
void gemm_fused(const __half* __restrict__ Ahi, const __half* __restrict__ Alo,
                const __half* __restrict__ Bhi, const float* __restrict__ bias,
                const float* __restrict__ w2, float* __restrict__ part)
{
    extern __shared__ __align__(1024) char sm[];
    constexpr uint32_t BOFF = 16384u, STGB = 24576u;
    const int tid = threadIdx.x, lane = tid & 31, warp = tid >> 5;
    const int m0 = blockIdx.y * 128, n0 = blockIdx.x * 128;
    const int wm = (warp & 1) * 64, wn = (warp >> 1) * 32;
    const uint32_t sbase = s2u(sm);

    auto load_tile = [&](int t){
        const uint32_t st = sbase + (uint32_t)(t % 3) * STGB;
        const int k0 = t * 32;
        #pragma unroll
        for (int i = 0; i < 4; i++){
            int g = tid + i * 256;
            int row = g >> 3, slot = g & 7;
            int pl = slot >> 2, gg = slot & 3;
            uint32_t d = SWZ((uint32_t)(row * 128 + pl * 64 + gg * 16));
            const __half* src = (pl ? Alo : Ahi) + (size_t)(m0 + row) * KDIM + k0 + gg * 8;
            CP16(st + d, src);
        }
        #pragma unroll
        for (int i = 0; i < 2; i++){
            int g = tid + i * 256;
            int row = g >> 2, gg = g & 3;
            uint32_t d = SWZ64((uint32_t)(row * 64 + gg * 16));
            CP16(st + BOFF + d, Bhi + (size_t)(n0 + row) * KDIM + k0 + gg * 8);
        }
        asm volatile("cp.async.commit_group;" ::: "memory");
    };

    float acc[4][4][4];
    #pragma unroll
    for (int mi = 0; mi < 4; mi++)
        #pragma unroll
        for (int ni = 0; ni < 4; ni++)
            #pragma unroll
            for (int r = 0; r < 4; r++) acc[mi][ni][r] = 0.0f;

    load_tile(0);
    load_tile(1);

    const uint32_t aRow = (uint32_t)(lane & 15);
    const uint32_t aCol = (uint32_t)(lane >> 4) * 16u;
    const uint32_t bRow = (uint32_t)(((lane >> 4) & 1) * 8 + (lane & 7));
    const uint32_t bCol = (uint32_t)((lane >> 3) & 1) * 16u;

    #pragma unroll 1
    for (int t = 0; t < NCH2; t++){
        if (t < NCH2 - 1) asm volatile("cp.async.wait_group 1;" ::: "memory");
        else              asm volatile("cp.async.wait_group 0;" ::: "memory");
        __syncthreads();
        if (t + 2 < NCH2) load_tile(t + 2);

        const uint32_t sA = sbase + (uint32_t)(t % 3) * STGB;
        const uint32_t sB = sA + BOFF;

        #pragma unroll
        for (int kk = 0; kk < 2; kk++){
            const uint32_t kb = (uint32_t)kk * 32u;
            uint32_t a[4][4], bh[8];
            #pragma unroll
            for (int np = 0; np < 2; np++){
                uint32_t ad = sB + SWZ64((uint32_t)((wn + np*16 + bRow) * 64) + kb + bCol);
                asm volatile("ldmatrix.sync.aligned.m8n8.x4.shared.b16 {%0,%1,%2,%3},[%4];"
                    : "=r"(bh[np*4]), "=r"(bh[np*4+1]), "=r"(bh[np*4+2]), "=r"(bh[np*4+3]) : "r"(ad));
            }
            #pragma unroll
            for (int mi = 0; mi < 4; mi++){
                uint32_t ad = sA + SWZ((uint32_t)((wm + mi*16 + aRow) * 128) + kb + aCol);
                asm volatile("ldmatrix.sync.aligned.m8n8.x4.shared.b16 {%0,%1,%2,%3},[%4];"
                    : "=r"(a[mi][0]), "=r"(a[mi][1]), "=r"(a[mi][2]), "=r"(a[mi][3]) : "r"(ad));
            }
            #pragma unroll
            for (int mi = 0; mi < 4; mi++)
                #pragma unroll
                for (int ni = 0; ni < 4; ni++)
                    mma16816(acc[mi][ni], a[mi], bh[(ni>>1)*4 + (ni&1)*2], bh[(ni>>1)*4 + (ni&1)*2 + 1]);
            #pragma unroll
            for (int mi = 0; mi < 4; mi++){
                uint32_t ad = sA + SWZ((uint32_t)((wm + mi*16 + aRow) * 128) + 64u + kb + aCol);
                asm volatile("ldmatrix.sync.aligned.m8n8.x4.shared.b16 {%0,%1,%2,%3},[%4];"
                    : "=r"(a[mi][0]), "=r"(a[mi][1]), "=r"(a[mi][2]), "=r"(a[mi][3]) : "r"(ad));
            }
            #pragma unroll
            for (int mi = 0; mi < 4; mi++)
                #pragma unroll
                for (int ni = 0; ni < 4; ni++)
                    mma16816(acc[mi][ni], a[mi], bh[(ni>>1)*4 + (ni&1)*2], bh[(ni>>1)*4 + (ni&1)*2 + 1]);
        }
    }

    const int erow = lane >> 2;
    const int ecol = (lane & 3) * 2;
    const int slot = blockIdx.x * 4 + (warp >> 1);
    #pragma unroll
    for (int mi = 0; mi < 4; mi++){
        float rs0 = 0.f, rs1 = 0.f;
        #pragma unroll
        for (int ni = 0; ni < 4; ni++){
            const int col = n0 + wn + ni * 8 + ecol;
            const float b0 = bias[col], b1 = bias[col + 1];
            const float w0 = w2[col],   w1 = w2[col + 1];
            rs0 += fmaxf(acc[mi][ni][0] + b0, 0.f) * w0
                 + fmaxf(acc[mi][ni][1] + b1, 0.f) * w1;
            rs1 += fmaxf(acc[mi][ni][2] + b0, 0.f) * w0
                 + fmaxf(acc[mi][ni][3] + b1, 0.f) * w1;
        }
        rs0 += __shfl_xor_sync(0xFFFFFFFFu, rs0, 1);
        rs0 += __shfl_xor_sync(0xFFFFFFFFu, rs0, 2);
        rs1 += __shfl_xor_sync(0xFFFFFFFFu, rs1, 1);
        rs1 += __shfl_xor_sync(0xFFFFFFFFu, rs1, 2);
        if ((lane & 3) == 0){
            const int row = m0 + wm + mi * 16 + erow;
            part[(size_t)row * 12 + slot]       = rs0;
            part[(size_t)(row + 8) * 12 + slot] = rs1;
        }
    }
}

// ---------------- attention over axis-0 (16) per (s,h), fp16 I/O -----------
__global__ __launch_bounds__(128)
void attn_kernel(){
    const int s = blockIdx.x, h = blockIdx.y, tid = threadIdx.x;
    __shared__ float q[16][100], k[16][100], v[16][100];
    __shared__ float sc[16][17];

    // load q/k/v: 16 rows x 96 halves each = 12 8-half chunks per row,
    // 576 chunks total (192 per tensor)
    const __half* srcbase = g_qkvh + (size_t)s*2304 + h*DHEAD;
    for (int c = tid; c < 576; c += 128){
        int tsr = c / 192, w = c % 192;
        int l = w / 12, cc = w % 12;
        const __half* p = srcbase + (size_t)l * ((size_t)SSEQ * 2304) + tsr * 768 + cc * 8;
        uint4 raw = *(const uint4*)p;
        float* dst = (tsr == 0 ? &q[l][cc*8] : (tsr == 1 ? &k[l][cc*8] : &v[l][cc*8]));
        __half2 p0 = *(__half2*)&raw.x, p1 = *(__half2*)&raw.y;
        __half2 p2 = *(__half2*)&raw.z, p3 = *(__half2*)&raw.w;
        float2 f0 = __half22float2(p0), f1 = __half22float2(p1);
        float2 f2 = __half22float2(p2), f3 = __half22float2(p3);
        dst[0]=f0.x; dst[1]=f0.y; dst[2]=f1.x; dst[3]=f1.y;
        dst[4]=f2.x; dst[5]=f2.y; dst[6]=f3.x; dst[7]=f3.y;
    }
    __syncthreads();

    const float scale = rsqrtf((float)DHEAD);
    #pragma unroll
    for (int i = 0; i < 2; i++){
        int idx = tid + i * 128;
        int l = idx >> 4, m = idx & 15;
        float acc = 0.f;
        #pragma unroll
        for (int d = 0; d < DHEAD; d++) acc = fmaf(q[l][d], k[m][d], acc);
        sc[l][m] = acc * scale;
    }
    __syncthreads();

    if (tid < 16){
        float mx = -INFINITY;
        #pragma unroll
        for (int m = 0; m < 16; m++) mx = fmaxf(mx, sc[tid][m]);
        float sum = 0.f;
        #pragma unroll
        for (int m = 0; m < 16; m++){ float e = expf(sc[tid][m]-mx); sc[tid][m]=e; sum+=e; }
        float inv = 1.f/sum;
        #pragma unroll
        for (int m = 0; m < 16; m++) sc[tid][m] *= inv;
    }
    __syncthreads();

    #pragma unroll
    for (int i = 0; i < 6; i++){
        int idx = tid + i * 128;
        int l = idx / 48, dp = idx % 48;
        int d = dp * 2;
        float a0 = 0.f, a1 = 0.f;
        #pragma unroll
        for (int m = 0; m < 16; m++){
            float w = sc[l][m];
            a0 = fmaf(w, v[m][d],   a0);
            a1 = fmaf(w, v[m][d+1], a1);
        }
        size_t o = ((size_t)l*SSEQ + s)*EMB + h*DHEAD + d;
        *(__half2*)(g_chi + o) = __halves2half2(__float2half(a0), __float2half(a1));
    }
}

// ---------------- broadcast: out[r,:] = sum(part[r]) + b2 -------------------
__global__ __launch_bounds__(256)
void bcast(const float* __restrict__ part, const float* __restrict__ b2,
           float* __restrict__ out){
    const int r = blockIdx.x * 2 + (threadIdx.x >> 7);
    const int t = threadIdx.x & 127;
    float p = b2[0];
    #pragma unroll
    for (int s = 0; s < 12; s++) p += part[(size_t)r * 12 + s];
    float4 p4 = make_float4(p, p, p, p);
    float4* orow = (float4*)(out + (size_t)r * SSEQ);
    #pragma unroll
    for (int i = 0; i < 4; i++) orow[t + i*128] = p4;
}

// ---------------------------------------------------------------------------
extern "C" void kernel_launch(void* const* d_in, const int* in_sizes, int n_in,
                              void* d_out, int out_size){
    const float* features = (const float*)d_in[0];
    const float* in_w  = (const float*)d_in[1];
    const float* in_b  = (const float*)d_in[2];
    const float* out_w = (const float*)d_in[3];
    const float* out_b = (const float*)d_in[4];
    const float* w1    = (const float*)d_in[5];
    const float* b1    = (const float*)d_in[6];
    const float* w2    = (const float*)d_in[7];
    const float* b2    = (const float*)d_in[8];
    float* out = (float*)d_out;

    float *pt;
    __half *qkvh,*fhi,*chi,*ohi,*olo,*whi;
    cudaGetSymbolAddress((void**)&qkvh, g_qkvh);
    cudaGetSymbolAddress((void**)&pt,  g_part);
    cudaGetSymbolAddress((void**)&fhi, g_fhi);
    cudaGetSymbolAddress((void**)&chi, g_chi);
    cudaGetSymbolAddress((void**)&ohi, g_ohi);
    cudaGetSymbolAddress((void**)&olo, g_olo);
    cudaGetSymbolAddress((void**)&whi, g_whi);

    const size_t OFF_OW = (size_t)2304*KDIM;
    const size_t OFF_W1 = (size_t)(2304+768)*KDIM;

    const int SMEM1 = 3 * 32768;
    const int SMEM2 = 3 * 24576;
    cudaFuncSetAttribute(gemm_1p<3>, cudaFuncAttributeMaxDynamicSharedMemorySize, SMEM1);
    cudaFuncSetAttribute(gemm_1p<2>, cudaFuncAttributeMaxDynamicSharedMemorySize, SMEM1);
    cudaFuncSetAttribute(gemm_fused, cudaFuncAttributeMaxDynamicSharedMemorySize, SMEM2);

    // launches 1-3: converts (keeps QKV gemm in profiled slot #4)
    {
        size_t n4 = (size_t)MROWS*KDIM/4;
        conv4<<<(unsigned)((n4+255)/256), 256>>>(features, fhi, n4);
        n4 = (size_t)2304*KDIM/4;
        conv4<<<(unsigned)((n4+255)/256), 256>>>(in_w, whi, n4);
        size_t na4 = (size_t)768*KDIM/4, nb4 = (size_t)384*KDIM/4;
        conv4x2<<<(unsigned)((na4+nb4+255)/256), 256>>>(
            out_w, whi+OFF_OW, na4, w1, whi+OFF_W1, nb4);
    }

    // 4) QKV = features @ in_w^T + in_b  -> fp16 (single 1-pass GEMM, N=2304)
    gemm_1p<3><<<dim3(2304/128, MROWS/128), 256, SMEM1>>>(
        fhi, whi, in_b, qkvh, nullptr, 2304);

    // 5) attention -> ctx (fp16)
    attn_kernel<<<dim3(SSEQ, NHEAD), 128>>>();

    // 6) att = ctx @ out_w^T + out_b -> fp16 hi/lo planes (1-pass)
    gemm_1p<2><<<dim3(768/128, MROWS/128), 256, SMEM1>>>(
        chi, whi+OFF_OW, out_b, ohi, olo, 768);

    // 7) fused: relu(att @ w1^T + b1) . w2  -> 12 partials per row
    gemm_fused<<<dim3(384/128, MROWS/128), 256, SMEM2>>>(
        ohi, olo, whi+OFF_W1, b1, w2, pt);

    // 8) broadcast (sums partials + b2)
    bcast<<<MROWS/2, 256>>>(pt, b2, out);
}

// round 12
// speedup vs baseline: 1.0947x; 1.0947x over previous
#include <cuda_runtime.h>
#include <cuda_fp16.h>
#include <math.h>
#include <stdint.h>

#define BBATCH 16
#define SSEQ   2048
#define EMB    768
#define NHEAD  8
#define DHEAD  96
#define MROWS  (BBATCH*SSEQ)   // 32768
#define KDIM   768
#define NCH1   12              // 768 / 64  (1-pass, BK=64)

// ---------------- scratch (device globals; allocation-free rule) -----------
__device__ __half  g_qkvh[(size_t)MROWS*2304];   // fp16 qkv
__device__ __half  g_fhi[(size_t)MROWS*KDIM];
__device__ __half  g_chi[(size_t)MROWS*KDIM];
__device__ __half  g_ohi[(size_t)MROWS*KDIM];
__device__ float   g_part[(size_t)MROWS*12];
__device__ __half  g_whi[(size_t)(2304+768+384)*KDIM];

// ---------------- helpers ---------------------------------------------------
__device__ __forceinline__ uint32_t s2u(const void* p){
    uint32_t a;
    asm("{ .reg .u64 t; cvta.to.shared.u64 t, %1; cvt.u32.u64 %0, t; }":"=r"(a):"l"(p));
    return a;
}
#define SWZ(o)   ((o) ^ (((o) >> 3) & 0x70))
#define CP16(s, g) asm volatile("cp.async.cg.shared.global [%0], [%1], 16;"::"r"(s),"l"(g):"memory")

__device__ __forceinline__ void mma16816(float* c, const uint32_t* a, uint32_t b0, uint32_t b1){
    asm volatile("mma.sync.aligned.m16n8k16.row.col.f32.f16.f16.f32 "
        "{%0,%1,%2,%3},{%4,%5,%6,%7},{%8,%9},{%0,%1,%2,%3};"
        : "+f"(c[0]), "+f"(c[1]), "+f"(c[2]), "+f"(c[3])
        : "r"(a[0]), "r"(a[1]), "r"(a[2]), "r"(a[3]), "r"(b0), "r"(b1));
}

// ---------------- fp32 -> fp16 convert, vectorized x4 ----------------------
__global__ __launch_bounds__(256)
void conv4(const float* __restrict__ src, __half* __restrict__ hi, size_t n4){
    size_t i = (size_t)blockIdx.x * blockDim.x + threadIdx.x;
    if (i >= n4) return;
    float4 v = ((const float4*)src)[i];
    ((__half2*)hi)[2*i]   = __halves2half2(__float2half(v.x), __float2half(v.y));
    ((__half2*)hi)[2*i+1] = __halves2half2(__float2half(v.z), __float2half(v.w));
}

__global__ __launch_bounds__(256)
void conv4x2(const float* __restrict__ sa, __half* __restrict__ ha, size_t na4,
             const float* __restrict__ sb, __half* __restrict__ hb, size_t nb4){
    size_t i = (size_t)blockIdx.x * blockDim.x + threadIdx.x;
    const float* src; __half* hi;
    if (i < na4){ src = sa; hi = ha; }
    else if (i < na4 + nb4){ i -= na4; src = sb; hi = hb; }
    else return;
    float4 v = ((const float4*)src)[i];
    ((__half2*)hi)[2*i]   = __halves2half2(__float2half(v.x), __float2half(v.y));
    ((__half2*)hi)[2*i+1] = __halves2half2(__float2half(v.z), __float2half(v.w));
}

// ---------------- 1-pass GEMM: C = A @ B^T + bias -> fp16, BK=64 -----------
// CTA 128x128, 256 thr, occ 2, 3-stage ring.
__global__ __launch_bounds__(256, 2)
void gemm_1p(const __half* __restrict__ Ahi, const __half* __restrict__ Bhi,
             const float* __restrict__ bias, __half* __restrict__ Chi, int N)
{
    extern __shared__ __align__(1024) char sm[];
    constexpr uint32_t STGB = 32768u;
    const int tid = threadIdx.x, lane = tid & 31, warp = tid >> 5;
    const int m0 = blockIdx.y * 128, n0 = blockIdx.x * 128;
    const int wm = (warp & 1) * 64, wn = (warp >> 1) * 32;
    const uint32_t sbase = s2u(sm);

    auto load_tile = [&](int t){
        const uint32_t st = sbase + (uint32_t)(t % 3) * STGB;
        const int k0 = t * 64;
        #pragma unroll
        for (int i = 0; i < 4; i++){
            int g = tid + i * 256;
            int row = g >> 3, gg = g & 7;
            uint32_t d = SWZ((uint32_t)(row * 128 + gg * 16));
            CP16(st + d, Ahi + (size_t)(m0 + row) * KDIM + k0 + gg * 8);
        }
        #pragma unroll
        for (int i = 0; i < 4; i++){
            int g = tid + i * 256;
            int row = g >> 3, gg = g & 7;
            uint32_t d = SWZ((uint32_t)(row * 128 + gg * 16));
            CP16(st + 16384u + d, Bhi + (size_t)(n0 + row) * KDIM + k0 + gg * 8);
        }
        asm volatile("cp.async.commit_group;" ::: "memory");
    };

    float acc[4][4][4];
    #pragma unroll
    for (int mi = 0; mi < 4; mi++)
        #pragma unroll
        for (int ni = 0; ni < 4; ni++)
            #pragma unroll
            for (int r = 0; r < 4; r++) acc[mi][ni][r] = 0.0f;

    load_tile(0);
    load_tile(1);

    const uint32_t aRow = (uint32_t)(lane & 15);
    const uint32_t aCol = (uint32_t)(lane >> 4) * 16u;
    const uint32_t bRow = (uint32_t)(((lane >> 4) & 1) * 8 + (lane & 7));
    const uint32_t bCol = (uint32_t)((lane >> 3) & 1) * 16u;

    #pragma unroll 1
    for (int t = 0; t < NCH1; t++){
        if (t < NCH1 - 1) asm volatile("cp.async.wait_group 1;" ::: "memory");
        else              asm volatile("cp.async.wait_group 0;" ::: "memory");
        __syncthreads();
        if (t + 2 < NCH1) load_tile(t + 2);

        const uint32_t sA = sbase + (uint32_t)(t % 3) * STGB;
        const uint32_t sB = sA + 16384u;

        #pragma unroll
        for (int kk = 0; kk < 4; kk++){
            const uint32_t kb = (uint32_t)kk * 32u;
            uint32_t a[4][4], bh[8];
            #pragma unroll
            for (int np = 0; np < 2; np++){
                uint32_t ad = sB + SWZ((uint32_t)((wn + np*16 + bRow) * 128) + kb + bCol);
                asm volatile("ldmatrix.sync.aligned.m8n8.x4.shared.b16 {%0,%1,%2,%3},[%4];"
                    : "=r"(bh[np*4]), "=r"(bh[np*4+1]), "=r"(bh[np*4+2]), "=r"(bh[np*4+3]) : "r"(ad));
            }
            #pragma unroll
            for (int mi = 0; mi < 4; mi++){
                uint32_t ad = sA + SWZ((uint32_t)((wm + mi*16 + aRow) * 128) + kb + aCol);
                asm volatile("ldmatrix.sync.aligned.m8n8.x4.shared.b16 {%0,%1,%2,%3},[%4];"
                    : "=r"(a[mi][0]), "=r"(a[mi][1]), "=r"(a[mi][2]), "=r"(a[mi][3]) : "r"(ad));
            }
            #pragma unroll
            for (int mi = 0; mi < 4; mi++)
                #pragma unroll
                for (int ni = 0; ni < 4; ni++)
                    mma16816(acc[mi][ni], a[mi], bh[(ni>>1)*4 + (ni&1)*2], bh[(ni>>1)*4 + (ni&1)*2 + 1]);
        }
    }

    const int erow = lane >> 2;
    const int ecol = (lane & 3) * 2;
    #pragma unroll
    for (int mi = 0; mi < 4; mi++){
        #pragma unroll
        for (int ni = 0; ni < 4; ni++){
            const int row = m0 + wm + mi * 16 + erow;
            const int col = n0 + wn + ni * 8 + ecol;
            const float b0 = bias[col], b1 = bias[col + 1];
            float v0 = acc[mi][ni][0] + b0, v1 = acc[mi][ni][1] + b1;
            float v2 = acc[mi][ni][2] + b0, v3 = acc[mi][ni][3] + b1;
            *(__half2*)(Chi + (size_t)row * N + col)
                = __halves2half2(__float2half(v0), __float2half(v1));
            *(__half2*)(Chi + (size_t)(row + 8) * N + col)
                = __halves2half2(__float2half(v2), __float2half(v3));
        }
    }
}

// ---------------- fused MLP: 1-pass BK=64, epilogue dots w2 -----------------
// part[row*12 + blockIdx.x*4 + (warp>>1)] = partial dot (deterministic).
__global__ __launch_bounds__(256, 2)
void gemm_fused(const __half* __restrict__ Ahi, const __half* __restrict__ Bhi,
                const float* __restrict__ bias, const float* __restrict__ w2,
                float* __restrict__ part)
{
    extern __shared__ __align__(1024) char sm[];
    constexpr uint32_t STGB = 32768u;
    const int tid = threadIdx.x, lane = tid & 31, warp = tid >> 5;
    const int m0 = blockIdx.y * 128, n0 = blockIdx.x * 128;
    const int wm = (warp & 1) * 64, wn = (warp >> 1) * 32;
    const uint32_t sbase = s2u(sm);

    auto load_tile = [&](int t){
        const uint32_t st = sbase + (uint32_t)(t % 3) * STGB;
        const int k0 = t * 64;
        #pragma unroll
        for (int i = 0; i < 4; i++){
            int g = tid + i * 256;
            int row = g >> 3, gg = g & 7;
            uint32_t d = SWZ((uint32_t)(row * 128 + gg * 16));
            CP16(st + d, Ahi + (size_t)(m0 + row) * KDIM + k0 + gg * 8);
        }
        #pragma unroll
        for (int i = 0; i < 4; i++){
            int g = tid + i * 256;
            int row = g >> 3, gg = g & 7;
            uint32_t d = SWZ((uint32_t)(row * 128 + gg * 16));
            CP16(st + 16384u + d, Bhi + (size_t)(n0 + row) * KDIM + k0 + gg * 8);
        }
        asm volatile("cp.async.commit_group;" ::: "memory");
    };

    float acc[4][4][4];
    #pragma unroll
    for (int mi = 0; mi < 4; mi++)
        #pragma unroll
        for (int ni = 0; ni < 4; ni++)
            #pragma unroll
            for (int r = 0; r < 4; r++) acc[mi][ni][r] = 0.0f;

    load_tile(0);
    load_tile(1);

    const uint32_t aRow = (uint32_t)(lane & 15);
    const uint32_t aCol = (uint32_t)(lane >> 4) * 16u;
    const uint32_t bRow = (uint32_t)(((lane >> 4) & 1) * 8 + (lane & 7));
    const uint32_t bCol = (uint32_t)((lane >> 3) & 1) * 16u;

    #pragma unroll 1
    for (int t = 0; t < NCH1; t++){
        if (t < NCH1 - 1) asm volatile("cp.async.wait_group 1;" ::: "memory");
        else              asm volatile("cp.async.wait_group 0;" ::: "memory");
        __syncthreads();
        if (t + 2 < NCH1) load_tile(t + 2);

        const uint32_t sA = sbase + (uint32_t)(t % 3) * STGB;
        const uint32_t sB = sA + 16384u;

        #pragma unroll
        for (int kk = 0; kk < 4; kk++){
            const uint32_t kb = (uint32_t)kk * 32u;
            uint32_t a[4][4], bh[8];
            #pragma unroll
            for (int np = 0; np < 2; np++){
                uint32_t ad = sB + SWZ((uint32_t)((wn + np*16 + bRow) * 128) + kb + bCol);
                asm volatile("ldmatrix.sync.aligned.m8n8.x4.shared.b16 {%0,%1,%2,%3},[%4];"
                    : "=r"(bh[np*4]), "=r"(bh[np*4+1]), "=r"(bh[np*4+2]), "=r"(bh[np*4+3]) : "r"(ad));
            }
            #pragma unroll
            for (int mi = 0; mi < 4; mi++){
                uint32_t ad = sA + SWZ((uint32_t)((wm + mi*16 + aRow) * 128) + kb + aCol);
                asm volatile("ldmatrix.sync.aligned.m8n8.x4.shared.b16 {%0,%1,%2,%3},[%4];"
                    : "=r"(a[mi][0]), "=r"(a[mi][1]), "=r"(a[mi][2]), "=r"(a[mi][3]) : "r"(ad));
            }
            #pragma unroll
            for (int mi = 0; mi < 4; mi++)
                #pragma unroll
                for (int ni = 0; ni < 4; ni++)
                    mma16816(acc[mi][ni], a[mi], bh[(ni>>1)*4 + (ni&1)*2], bh[(ni>>1)*4 + (ni&1)*2 + 1]);
        }
    }

    const int erow = lane >> 2;
    const int ecol = (lane & 3) * 2;
    const int slot = blockIdx.x * 4 + (warp >> 1);
    #pragma unroll
    for (int mi = 0; mi < 4; mi++){
        float rs0 = 0.f, rs1 = 0.f;
        #pragma unroll
        for (int ni = 0; ni < 4; ni++){
            const int col = n0 + wn + ni * 8 + ecol;
            const float b0 = bias[col], b1 = bias[col + 1];
            const float w0 = w2[col],   w1 = w2[col + 1];
            rs0 += fmaxf(acc[mi][ni][0] + b0, 0.f) * w0
                 + fmaxf(acc[mi][ni][1] + b1, 0.f) * w1;
            rs1 += fmaxf(acc[mi][ni][2] + b0, 0.f) * w0
                 + fmaxf(acc[mi][ni][3] + b1, 0.f) * w1;
        }
        rs0 += __shfl_xor_sync(0xFFFFFFFFu, rs0, 1);
        rs0 += __shfl_xor_sync(0xFFFFFFFFu, rs0, 2);
        rs1 += __shfl_xor_sync(0xFFFFFFFFu, rs1, 1);
        rs1 += __shfl_xor_sync(0xFFFFFFFFu, rs1, 2);
        if ((lane & 3) == 0){
            const int row = m0 + wm + mi * 16 + erow;
            part[(size_t)row * 12 + slot]       = rs0;
            part[(size_t)(row + 8) * 12 + slot] = rs1;
        }
    }
}

// ---------------- attention: 192 threads, clean fp16 loads -----------------
__global__ __launch_bounds__(192)
void attn_kernel(){
    const int s = blockIdx.x, h = blockIdx.y, tid = threadIdx.x;
    __shared__ float q[16][100], k[16][100], v[16][100];
    __shared__ float sc[16][17];

    // 3 iterations: i selects tensor (q/k/v); (l, cc) constant per thread.
    const int l  = tid / 12;          // row 0..15
    const int cc = tid % 12;          // 8-half chunk 0..11
    const __half* srcrow = g_qkvh + (size_t)l * ((size_t)SSEQ * 2304)
                         + (size_t)s * 2304 + h * DHEAD + cc * 8;
    #pragma unroll
    for (int i = 0; i < 3; i++){
        uint4 raw = *(const uint4*)(srcrow + i * 768);
        float* dst = (i == 0 ? &q[l][cc*8] : (i == 1 ? &k[l][cc*8] : &v[l][cc*8]));
        float2 f0 = __half22float2(*(__half2*)&raw.x);
        float2 f1 = __half22float2(*(__half2*)&raw.y);
        float2 f2 = __half22float2(*(__half2*)&raw.z);
        float2 f3 = __half22float2(*(__half2*)&raw.w);
        dst[0]=f0.x; dst[1]=f0.y; dst[2]=f1.x; dst[3]=f1.y;
        dst[4]=f2.x; dst[5]=f2.y; dst[6]=f3.x; dst[7]=f3.y;
    }
    __syncthreads();

    const float scale = rsqrtf((float)DHEAD);
    {   // 256 scores over 192 threads: 192 + 64
        int idx = tid;
        int sl = idx >> 4, m = idx & 15;
        float acc = 0.f;
        #pragma unroll
        for (int d = 0; d < DHEAD; d++) acc = fmaf(q[sl][d], k[m][d], acc);
        sc[sl][m] = acc * scale;
        if (tid < 64){
            idx = 192 + tid;
            sl = idx >> 4; m = idx & 15;
            acc = 0.f;
            #pragma unroll
            for (int d = 0; d < DHEAD; d++) acc = fmaf(q[sl][d], k[m][d], acc);
            sc[sl][m] = acc * scale;
        }
    }
    __syncthreads();

    if (tid < 16){
        float mx = -INFINITY;
        #pragma unroll
        for (int m = 0; m < 16; m++) mx = fmaxf(mx, sc[tid][m]);
        float sum = 0.f;
        #pragma unroll
        for (int m = 0; m < 16; m++){ float e = expf(sc[tid][m]-mx); sc[tid][m]=e; sum+=e; }
        float inv = 1.f/sum;
        #pragma unroll
        for (int m = 0; m < 16; m++) sc[tid][m] *= inv;
    }
    __syncthreads();

    // ctx: 768 half2 pairs over 192 threads = 4 exact iterations
    #pragma unroll
    for (int i = 0; i < 4; i++){
        int idx = tid + i * 192;
        int cl = idx / 48, dp = idx % 48;
        int d = dp * 2;
        float a0 = 0.f, a1 = 0.f;
        #pragma unroll
        for (int m = 0; m < 16; m++){
            float w = sc[cl][m];
            a0 = fmaf(w, v[m][d],   a0);
            a1 = fmaf(w, v[m][d+1], a1);
        }
        size_t o = ((size_t)cl*SSEQ + s)*EMB + h*DHEAD + d;
        *(__half2*)(g_chi + o) = __halves2half2(__float2half(a0), __float2half(a1));
    }
}

// ---------------- broadcast: out[r,:] = sum(part[r]) + b2 -------------------
__global__ __launch_bounds__(256)
void bcast(const float* __restrict__ part, const float* __restrict__ b2,
           float* __restrict__ out){
    const int r = blockIdx.x * 2 + (threadIdx.x >> 7);
    const int t = threadIdx.x & 127;
    float p = b2[0];
    #pragma unroll
    for (int s = 0; s < 12; s++) p += part[(size_t)r * 12 + s];
    float4 p4 = make_float4(p, p, p, p);
    float4* orow = (float4*)(out + (size_t)r * SSEQ);
    #pragma unroll
    for (int i = 0; i < 4; i++) orow[t + i*128] = p4;
}

// ---------------------------------------------------------------------------
extern "C" void kernel_launch(void* const* d_in, const int* in_sizes, int n_in,
                              void* d_out, int out_size){
    const float* features = (const float*)d_in[0];
    const float* in_w  = (const float*)d_in[1];
    const float* in_b  = (const float*)d_in[2];
    const float* out_w = (const float*)d_in[3];
    const float* out_b = (const float*)d_in[4];
    const float* w1    = (const float*)d_in[5];
    const float* b1    = (const float*)d_in[6];
    const float* w2    = (const float*)d_in[7];
    const float* b2    = (const float*)d_in[8];
    float* out = (float*)d_out;

    float *pt;
    __half *qkvh,*fhi,*chi,*ohi,*whi;
    cudaGetSymbolAddress((void**)&qkvh, g_qkvh);
    cudaGetSymbolAddress((void**)&pt,  g_part);
    cudaGetSymbolAddress((void**)&fhi, g_fhi);
    cudaGetSymbolAddress((void**)&chi, g_chi);
    cudaGetSymbolAddress((void**)&ohi, g_ohi);
    cudaGetSymbolAddress((void**)&whi, g_whi);

    const size_t OFF_OW = (size_t)2304*KDIM;
    const size_t OFF_W1 = (size_t)(2304+768)*KDIM;

    const int SMEM1 = 3 * 32768;
    cudaFuncSetAttribute(gemm_1p,    cudaFuncAttributeMaxDynamicSharedMemorySize, SMEM1);
    cudaFuncSetAttribute(gemm_fused, cudaFuncAttributeMaxDynamicSharedMemorySize, SMEM1);

    // launches 1-3: converts (keeps QKV gemm in profiled slot #4)
    {
        size_t n4 = (size_t)MROWS*KDIM/4;
        conv4<<<(unsigned)((n4+255)/256), 256>>>(features, fhi, n4);
        n4 = (size_t)2304*KDIM/4;
        conv4<<<(unsigned)((n4+255)/256), 256>>>(in_w, whi, n4);
        size_t na4 = (size_t)768*KDIM/4, nb4 = (size_t)384*KDIM/4;
        conv4x2<<<(unsigned)((na4+nb4+255)/256), 256>>>(
            out_w, whi+OFF_OW, na4, w1, whi+OFF_W1, nb4);
    }

    // 4) QKV = features @ in_w^T + in_b  -> fp16
    gemm_1p<<<dim3(2304/128, MROWS/128), 256, SMEM1>>>(
        fhi, whi, in_b, qkvh, 2304);

    // 5) attention -> ctx (fp16, 192-thread blocks)
    attn_kernel<<<dim3(SSEQ, NHEAD), 192>>>();

    // 6) att = ctx @ out_w^T + out_b -> fp16 (hi only)
    gemm_1p<<<dim3(768/128, MROWS/128), 256, SMEM1>>>(
        chi, whi+OFF_OW, out_b, ohi, 768);

    // 7) fused MLP: relu(att @ w1^T + b1) . w2 -> 12 partials/row (1-pass)
    gemm_fused<<<dim3(384/128, MROWS/128), 256, SMEM1>>>(
        ohi, whi+OFF_W1, b1, w2, pt);

    // 8) broadcast
    bcast<<<MROWS/2, 256>>>(pt, b2, out);
}

// round 13
// speedup vs baseline: 1.1216x; 1.0245x over previous
#include <cuda_runtime.h>
#include <cuda_fp16.h>
#include <math.h>
#include <stdint.h>

#define BBATCH 16
#define SSEQ   2048
#define EMB    768
#define NHEAD  8
#define DHEAD  96
#define MROWS  (BBATCH*SSEQ)   // 32768
#define KDIM   768
#define NCH1   12              // 768 / 64  (1-pass, BK=64)
#define ASTRIDE 2312           // smem row stride (halves), padded

// ---------------- scratch (device globals; allocation-free rule) -----------
__device__ __half  g_qkvh[(size_t)MROWS*2304];   // fp16 qkv
__device__ __half  g_fhi[(size_t)MROWS*KDIM];
__device__ __half  g_chi[(size_t)MROWS*KDIM];
__device__ __half  g_ohi[(size_t)MROWS*KDIM];
__device__ float   g_part[(size_t)MROWS*12];
__device__ __half  g_whi[(size_t)(2304+768+384)*KDIM];

// ---------------- helpers ---------------------------------------------------
__device__ __forceinline__ uint32_t s2u(const void* p){
    uint32_t a;
    asm("{ .reg .u64 t; cvta.to.shared.u64 t, %1; cvt.u32.u64 %0, t; }":"=r"(a):"l"(p));
    return a;
}
#define SWZ(o)   ((o) ^ (((o) >> 3) & 0x70))
#define CP16(s, g) asm volatile("cp.async.cg.shared.global [%0], [%1], 16;"::"r"(s),"l"(g):"memory")

__device__ __forceinline__ void mma16816(float* c, const uint32_t* a, uint32_t b0, uint32_t b1){
    asm volatile("mma.sync.aligned.m16n8k16.row.col.f32.f16.f16.f32 "
        "{%0,%1,%2,%3},{%4,%5,%6,%7},{%8,%9},{%0,%1,%2,%3};"
        : "+f"(c[0]), "+f"(c[1]), "+f"(c[2]), "+f"(c[3])
        : "r"(a[0]), "r"(a[1]), "r"(a[2]), "r"(a[3]), "r"(b0), "r"(b1));
}

// ---------------- fp32 -> fp16 converts -------------------------------------
__global__ __launch_bounds__(256)
void conv4(const float* __restrict__ src, __half* __restrict__ hi, size_t n4){
    size_t i = (size_t)blockIdx.x * blockDim.x + threadIdx.x;
    if (i >= n4) return;
    float4 v = ((const float4*)src)[i];
    ((__half2*)hi)[2*i]   = __halves2half2(__float2half(v.x), __float2half(v.y));
    ((__half2*)hi)[2*i+1] = __halves2half2(__float2half(v.z), __float2half(v.w));
}

// all three weight tensors -> contiguous whi in one launch
__global__ __launch_bounds__(256)
void conv_w(const float* __restrict__ wa, const float* __restrict__ wb,
            const float* __restrict__ wc, __half* __restrict__ dst){
    const size_t n0 = (size_t)2304*KDIM/4;   // in_w
    const size_t n1 = (size_t)768*KDIM/4;    // out_w
    const size_t n2 = (size_t)384*KDIM/4;    // w1
    size_t i = (size_t)blockIdx.x * blockDim.x + threadIdx.x;
    if (i >= n0 + n1 + n2) return;
    const float* src; size_t off;
    if (i < n0){ src = wa; off = i; }
    else if (i < n0 + n1){ src = wb; off = i - n0; }
    else { src = wc; off = i - n0 - n1; }
    float4 v = ((const float4*)src)[off];
    ((__half2*)dst)[2*i]   = __halves2half2(__float2half(v.x), __float2half(v.y));
    ((__half2*)dst)[2*i+1] = __halves2half2(__float2half(v.z), __float2half(v.w));
}

// ---------------- 1-pass GEMM: C = A @ B^T + bias -> fp16, BK=64 -----------
__global__ __launch_bounds__(256, 2)
void gemm_1p(const __half* __restrict__ Ahi, const __half* __restrict__ Bhi,
             const float* __restrict__ bias, __half* __restrict__ Chi, int N)
{
    extern __shared__ __align__(1024) char sm[];
    constexpr uint32_t STGB = 32768u;
    const int tid = threadIdx.x, lane = tid & 31, warp = tid >> 5;
    const int m0 = blockIdx.y * 128, n0 = blockIdx.x * 128;
    const int wm = (warp & 1) * 64, wn = (warp >> 1) * 32;
    const uint32_t sbase = s2u(sm);

    auto load_tile = [&](int t){
        const uint32_t st = sbase + (uint32_t)(t % 3) * STGB;
        const int k0 = t * 64;
        #pragma unroll
        for (int i = 0; i < 4; i++){
            int g = tid + i * 256;
            int row = g >> 3, gg = g & 7;
            uint32_t d = SWZ((uint32_t)(row * 128 + gg * 16));
            CP16(st + d, Ahi + (size_t)(m0 + row) * KDIM + k0 + gg * 8);
        }
        #pragma unroll
        for (int i = 0; i < 4; i++){
            int g = tid + i * 256;
            int row = g >> 3, gg = g & 7;
            uint32_t d = SWZ((uint32_t)(row * 128 + gg * 16));
            CP16(st + 16384u + d, Bhi + (size_t)(n0 + row) * KDIM + k0 + gg * 8);
        }
        asm volatile("cp.async.commit_group;" ::: "memory");
    };

    float acc[4][4][4];
    #pragma unroll
    for (int mi = 0; mi < 4; mi++)
        #pragma unroll
        for (int ni = 0; ni < 4; ni++)
            #pragma unroll
            for (int r = 0; r < 4; r++) acc[mi][ni][r] = 0.0f;

    load_tile(0);
    load_tile(1);

    const uint32_t aRow = (uint32_t)(lane & 15);
    const uint32_t aCol = (uint32_t)(lane >> 4) * 16u;
    const uint32_t bRow = (uint32_t)(((lane >> 4) & 1) * 8 + (lane & 7));
    const uint32_t bCol = (uint32_t)((lane >> 3) & 1) * 16u;

    #pragma unroll 1
    for (int t = 0; t < NCH1; t++){
        if (t < NCH1 - 1) asm volatile("cp.async.wait_group 1;" ::: "memory");
        else              asm volatile("cp.async.wait_group 0;" ::: "memory");
        __syncthreads();
        if (t + 2 < NCH1) load_tile(t + 2);

        const uint32_t sA = sbase + (uint32_t)(t % 3) * STGB;
        const uint32_t sB = sA + 16384u;

        #pragma unroll
        for (int kk = 0; kk < 4; kk++){
            const uint32_t kb = (uint32_t)kk * 32u;
            uint32_t a[4][4], bh[8];
            #pragma unroll
            for (int np = 0; np < 2; np++){
                uint32_t ad = sB + SWZ((uint32_t)((wn + np*16 + bRow) * 128) + kb + bCol);
                asm volatile("ldmatrix.sync.aligned.m8n8.x4.shared.b16 {%0,%1,%2,%3},[%4];"
                    : "=r"(bh[np*4]), "=r"(bh[np*4+1]), "=r"(bh[np*4+2]), "=r"(bh[np*4+3]) : "r"(ad));
            }
            #pragma unroll
            for (int mi = 0; mi < 4; mi++){
                uint32_t ad = sA + SWZ((uint32_t)((wm + mi*16 + aRow) * 128) + kb + aCol);
                asm volatile("ldmatrix.sync.aligned.m8n8.x4.shared.b16 {%0,%1,%2,%3},[%4];"
                    : "=r"(a[mi][0]), "=r"(a[mi][1]), "=r"(a[mi][2]), "=r"(a[mi][3]) : "r"(ad));
            }
            #pragma unroll
            for (int mi = 0; mi < 4; mi++)
                #pragma unroll
                for (int ni = 0; ni < 4; ni++)
                    mma16816(acc[mi][ni], a[mi], bh[(ni>>1)*4 + (ni&1)*2], bh[(ni>>1)*4 + (ni&1)*2 + 1]);
        }
    }

    const int erow = lane >> 2;
    const int ecol = (lane & 3) * 2;
    #pragma unroll
    for (int mi = 0; mi < 4; mi++){
        #pragma unroll
        for (int ni = 0; ni < 4; ni++){
            const int row = m0 + wm + mi * 16 + erow;
            const int col = n0 + wn + ni * 8 + ecol;
            const float b0 = bias[col], b1 = bias[col + 1];
            float v0 = acc[mi][ni][0] + b0, v1 = acc[mi][ni][1] + b1;
            float v2 = acc[mi][ni][2] + b0, v3 = acc[mi][ni][3] + b1;
            *(__half2*)(Chi + (size_t)row * N + col)
                = __halves2half2(__float2half(v0), __float2half(v1));
            *(__half2*)(Chi + (size_t)(row + 8) * N + col)
                = __halves2half2(__float2half(v2), __float2half(v3));
        }
    }
}

// ---------------- fused MLP: 1-pass BK=64, epilogue dots w2 -----------------
__global__ __launch_bounds__(256, 2)
void gemm_fused(const __half* __restrict__ Ahi, const __half* __restrict__ Bhi,
                const float* __restrict__ bias, const float* __restrict__ w2,
                float* __restrict__ part)
{
    extern __shared__ __align__(1024) char sm[];
    constexpr uint32_t STGB = 32768u;
    const int tid = threadIdx.x, lane = tid & 31, warp = tid >> 5;
    const int m0 = blockIdx.y * 128, n0 = blockIdx.x * 128;
    const int wm = (warp & 1) * 64, wn = (warp >> 1) * 32;
    const uint32_t sbase = s2u(sm);

    auto load_tile = [&](int t){
        const uint32_t st = sbase + (uint32_t)(t % 3) * STGB;
        const int k0 = t * 64;
        #pragma unroll
        for (int i = 0; i < 4; i++){
            int g = tid + i * 256;
            int row = g >> 3, gg = g & 7;
            uint32_t d = SWZ((uint32_t)(row * 128 + gg * 16));
            CP16(st + d, Ahi + (size_t)(m0 + row) * KDIM + k0 + gg * 8);
        }
        #pragma unroll
        for (int i = 0; i < 4; i++){
            int g = tid + i * 256;
            int row = g >> 3, gg = g & 7;
            uint32_t d = SWZ((uint32_t)(row * 128 + gg * 16));
            CP16(st + 16384u + d, Bhi + (size_t)(n0 + row) * KDIM + k0 + gg * 8);
        }
        asm volatile("cp.async.commit_group;" ::: "memory");
    };

    float acc[4][4][4];
    #pragma unroll
    for (int mi = 0; mi < 4; mi++)
        #pragma unroll
        for (int ni = 0; ni < 4; ni++)
            #pragma unroll
            for (int r = 0; r < 4; r++) acc[mi][ni][r] = 0.0f;

    load_tile(0);
    load_tile(1);

    const uint32_t aRow = (uint32_t)(lane & 15);
    const uint32_t aCol = (uint32_t)(lane >> 4) * 16u;
    const uint32_t bRow = (uint32_t)(((lane >> 4) & 1) * 8 + (lane & 7));
    const uint32_t bCol = (uint32_t)((lane >> 3) & 1) * 16u;

    #pragma unroll 1
    for (int t = 0; t < NCH1; t++){
        if (t < NCH1 - 1) asm volatile("cp.async.wait_group 1;" ::: "memory");
        else              asm volatile("cp.async.wait_group 0;" ::: "memory");
        __syncthreads();
        if (t + 2 < NCH1) load_tile(t + 2);

        const uint32_t sA = sbase + (uint32_t)(t % 3) * STGB;
        const uint32_t sB = sA + 16384u;

        #pragma unroll
        for (int kk = 0; kk < 4; kk++){
            const uint32_t kb = (uint32_t)kk * 32u;
            uint32_t a[4][4], bh[8];
            #pragma unroll
            for (int np = 0; np < 2; np++){
                uint32_t ad = sB + SWZ((uint32_t)((wn + np*16 + bRow) * 128) + kb + bCol);
                asm volatile("ldmatrix.sync.aligned.m8n8.x4.shared.b16 {%0,%1,%2,%3},[%4];"
                    : "=r"(bh[np*4]), "=r"(bh[np*4+1]), "=r"(bh[np*4+2]), "=r"(bh[np*4+3]) : "r"(ad));
            }
            #pragma unroll
            for (int mi = 0; mi < 4; mi++){
                uint32_t ad = sA + SWZ((uint32_t)((wm + mi*16 + aRow) * 128) + kb + aCol);
                asm volatile("ldmatrix.sync.aligned.m8n8.x4.shared.b16 {%0,%1,%2,%3},[%4];"
                    : "=r"(a[mi][0]), "=r"(a[mi][1]), "=r"(a[mi][2]), "=r"(a[mi][3]) : "r"(ad));
            }
            #pragma unroll
            for (int mi = 0; mi < 4; mi++)
                #pragma unroll
                for (int ni = 0; ni < 4; ni++)
                    mma16816(acc[mi][ni], a[mi], bh[(ni>>1)*4 + (ni&1)*2], bh[(ni>>1)*4 + (ni&1)*2 + 1]);
        }
    }

    const int erow = lane >> 2;
    const int ecol = (lane & 3) * 2;
    const int slot = blockIdx.x * 4 + (warp >> 1);
    #pragma unroll
    for (int mi = 0; mi < 4; mi++){
        float rs0 = 0.f, rs1 = 0.f;
        #pragma unroll
        for (int ni = 0; ni < 4; ni++){
            const int col = n0 + wn + ni * 8 + ecol;
            const float b0 = bias[col], b1 = bias[col + 1];
            const float w0 = w2[col],   w1 = w2[col + 1];
            rs0 += fmaxf(acc[mi][ni][0] + b0, 0.f) * w0
                 + fmaxf(acc[mi][ni][1] + b1, 0.f) * w1;
            rs1 += fmaxf(acc[mi][ni][2] + b0, 0.f) * w0
                 + fmaxf(acc[mi][ni][3] + b1, 0.f) * w1;
        }
        rs0 += __shfl_xor_sync(0xFFFFFFFFu, rs0, 1);
        rs0 += __shfl_xor_sync(0xFFFFFFFFu, rs0, 2);
        rs1 += __shfl_xor_sync(0xFFFFFFFFu, rs1, 1);
        rs1 += __shfl_xor_sync(0xFFFFFFFFu, rs1, 2);
        if ((lane & 3) == 0){
            const int row = m0 + wm + mi * 16 + erow;
            part[(size_t)row * 12 + slot]       = rs0;
            part[(size_t)(row + 8) * 12 + slot] = rs1;
        }
    }
}

// ---------------- attention: one block per s, ALL 8 heads -------------------
// Loads 16 rows x 2304 halves (4.5KB contiguous each) into 72KB fp16 smem,
// computes QK softmax PV for all heads from smem. Coalesced DRAM access.
__global__ __launch_bounds__(256)
void attn_kernel(){
    extern __shared__ __align__(16) char smraw[];
    __half* buf = (__half*)smraw;                        // [16][ASTRIDE]
    float*  sc  = (float*)(smraw + 16 * ASTRIDE * 2);    // [8][16][17]

    const int s = blockIdx.x, tid = threadIdx.x;

    // load: 16 rows x 288 uint4 = 4608 chunks
    for (int c = tid; c < 4608; c += 256){
        int l = c / 288, cc = c - l * 288;
        const __half* src = g_qkvh + (size_t)l * ((size_t)SSEQ * 2304)
                          + (size_t)s * 2304 + cc * 8;
        *(uint4*)(buf + l * ASTRIDE + cc * 8) = *(const uint4*)src;
    }
    __syncthreads();

    // scores: all 8 heads, thread -> (l, m)
    const float scale = rsqrtf((float)DHEAD);
    const int sl = tid >> 4, m = tid & 15;
    #pragma unroll
    for (int h = 0; h < NHEAD; h++){
        const __half2* q2 = (const __half2*)(buf + sl * ASTRIDE + h * DHEAD);
        const __half2* k2 = (const __half2*)(buf + m  * ASTRIDE + 768 + h * DHEAD);
        float acc = 0.f;
        #pragma unroll
        for (int d = 0; d < 48; d++){
            float2 fq = __half22float2(q2[d]);
            float2 fk = __half22float2(k2[d]);
            acc = fmaf(fq.x, fk.x, acc);
            acc = fmaf(fq.y, fk.y, acc);
        }
        sc[(h * 16 + sl) * 17 + m] = acc * scale;
    }
    __syncthreads();

    // softmax per (h, l): 128 rows
    if (tid < 128){
        float* row = &sc[tid * 17];
        float mx = -INFINITY;
        #pragma unroll
        for (int j = 0; j < 16; j++) mx = fmaxf(mx, row[j]);
        float sum = 0.f;
        #pragma unroll
        for (int j = 0; j < 16; j++){ float e = expf(row[j] - mx); row[j] = e; sum += e; }
        float inv = 1.f / sum;
        #pragma unroll
        for (int j = 0; j < 16; j++) row[j] *= inv;
    }
    __syncthreads();

    // PV: 16 l x 8 h x 48 dpairs = 6144 half2 outputs, 24 iters
    #pragma unroll
    for (int i = 0; i < 24; i++){
        int idx = tid + i * 256;
        int dp = idx % 48;
        int hl = idx / 48;            // 0..127
        int h  = hl & 7;
        int cl = hl >> 3;
        int d  = dp * 2;
        const float* scrow = &sc[(h * 16 + cl) * 17];
        float a0 = 0.f, a1 = 0.f;
        #pragma unroll
        for (int mm = 0; mm < 16; mm++){
            float w = scrow[mm];
            float2 fv = __half22float2(
                *(const __half2*)(buf + mm * ASTRIDE + 1536 + h * DHEAD + d));
            a0 = fmaf(w, fv.x, a0);
            a1 = fmaf(w, fv.y, a1);
        }
        size_t o = ((size_t)cl * SSEQ + s) * EMB + h * DHEAD + d;
        *(__half2*)(g_chi + o) = __halves2half2(__float2half(a0), __float2half(a1));
    }
}

// ---------------- broadcast: out[r,:] = sum(part[r]) + b2 -------------------
__global__ __launch_bounds__(256)
void bcast(const float* __restrict__ part, const float* __restrict__ b2,
           float* __restrict__ out){
    const int r = blockIdx.x * 2 + (threadIdx.x >> 7);
    const int t = threadIdx.x & 127;
    float p = b2[0];
    #pragma unroll
    for (int s = 0; s < 12; s++) p += part[(size_t)r * 12 + s];
    float4 p4 = make_float4(p, p, p, p);
    float4* orow = (float4*)(out + (size_t)r * SSEQ);
    #pragma unroll
    for (int i = 0; i < 4; i++) orow[t + i*128] = p4;
}

// ---------------------------------------------------------------------------
extern "C" void kernel_launch(void* const* d_in, const int* in_sizes, int n_in,
                              void* d_out, int out_size){
    const float* features = (const float*)d_in[0];
    const float* in_w  = (const float*)d_in[1];
    const float* in_b  = (const float*)d_in[2];
    const float* out_w = (const float*)d_in[3];
    const float* out_b = (const float*)d_in[4];
    const float* w1    = (const float*)d_in[5];
    const float* b1    = (const float*)d_in[6];
    const float* w2    = (const float*)d_in[7];
    const float* b2    = (const float*)d_in[8];
    float* out = (float*)d_out;

    float *pt;
    __half *qkvh,*fhi,*chi,*ohi,*whi;
    cudaGetSymbolAddress((void**)&qkvh, g_qkvh);
    cudaGetSymbolAddress((void**)&pt,  g_part);
    cudaGetSymbolAddress((void**)&fhi, g_fhi);
    cudaGetSymbolAddress((void**)&chi, g_chi);
    cudaGetSymbolAddress((void**)&ohi, g_ohi);
    cudaGetSymbolAddress((void**)&whi, g_whi);

    const size_t OFF_OW = (size_t)2304*KDIM;
    const size_t OFF_W1 = (size_t)(2304+768)*KDIM;

    const int SMEM1 = 3 * 32768;
    const int SMEMA = 16 * ASTRIDE * 2 + 8 * 16 * 17 * 4;   // 82688 B
    cudaFuncSetAttribute(gemm_1p,    cudaFuncAttributeMaxDynamicSharedMemorySize, SMEM1);
    cudaFuncSetAttribute(gemm_fused, cudaFuncAttributeMaxDynamicSharedMemorySize, SMEM1);
    cudaFuncSetAttribute(attn_kernel, cudaFuncAttributeMaxDynamicSharedMemorySize, SMEMA);

    // 1-2) converts
    {
        size_t n4 = (size_t)MROWS*KDIM/4;
        conv4<<<(unsigned)((n4+255)/256), 256>>>(features, fhi, n4);
        size_t nw4 = (size_t)(2304+768+384)*KDIM/4;
        conv_w<<<(unsigned)((nw4+255)/256), 256>>>(in_w, out_w, w1, whi);
    }

    // 3) QKV = features @ in_w^T + in_b  -> fp16
    gemm_1p<<<dim3(2304/128, MROWS/128), 256, SMEM1>>>(
        fhi, whi, in_b, qkvh, 2304);

    // 4) attention (profiled slot) -> ctx fp16
    attn_kernel<<<SSEQ, 256, SMEMA>>>();

    // 5) att = ctx @ out_w^T + out_b -> fp16
    gemm_1p<<<dim3(768/128, MROWS/128), 256, SMEM1>>>(
        chi, whi+OFF_OW, out_b, ohi, 768);

    // 6) fused MLP -> 12 partials/row
    gemm_fused<<<dim3(384/128, MROWS/128), 256, SMEM1>>>(
        ohi, whi+OFF_W1, b1, w2, pt);

    // 7) broadcast
    bcast<<<MROWS/2, 256>>>(pt, b2, out);
}

// round 14
// speedup vs baseline: 1.2604x; 1.1238x over previous
#include <cuda_runtime.h>
#include <cuda_fp16.h>
#include <math.h>
#include <stdint.h>

#define BBATCH 16
#define SSEQ   2048
#define EMB    768
#define NHEAD  8
#define DHEAD  96
#define MROWS  (BBATCH*SSEQ)   // 32768
#define KDIM   768
#define NCH1   12              // 768 / 64  (1-pass, BK=64)
#define ASTRIDE 2312           // attn smem row stride (halves)

// ---------------- scratch (device globals; allocation-free rule) -----------
__device__ __half  g_qkvh[(size_t)MROWS*2304];
__device__ __half  g_fhi[(size_t)MROWS*KDIM];
__device__ __half  g_chi[(size_t)MROWS*KDIM];
__device__ __half  g_ohi[(size_t)MROWS*KDIM];
__device__ float   g_part[(size_t)MROWS*12];
__device__ __half  g_whi[(size_t)(2304+768+384)*KDIM];

// ---------------- helpers ---------------------------------------------------
__device__ __forceinline__ uint32_t s2u(const void* p){
    uint32_t a;
    asm("{ .reg .u64 t; cvta.to.shared.u64 t, %1; cvt.u32.u64 %0, t; }":"=r"(a):"l"(p));
    return a;
}
#define SWZ(o)   ((o) ^ (((o) >> 3) & 0x70))
#define CP16(s, g) asm volatile("cp.async.cg.shared.global [%0], [%1], 16;"::"r"(s),"l"(g):"memory")

__device__ __forceinline__ void mma16816(float* c, const uint32_t* a, uint32_t b0, uint32_t b1){
    asm volatile("mma.sync.aligned.m16n8k16.row.col.f32.f16.f16.f32 "
        "{%0,%1,%2,%3},{%4,%5,%6,%7},{%8,%9},{%0,%1,%2,%3};"
        : "+f"(c[0]), "+f"(c[1]), "+f"(c[2]), "+f"(c[3])
        : "r"(a[0]), "r"(a[1]), "r"(a[2]), "r"(a[3]), "r"(b0), "r"(b1));
}

// ---------------- fp32 -> fp16 converts -------------------------------------
__global__ __launch_bounds__(256)
void conv4(const float* __restrict__ src, __half* __restrict__ hi, size_t n4){
    size_t i = (size_t)blockIdx.x * blockDim.x + threadIdx.x;
    if (i >= n4) return;
    float4 v = ((const float4*)src)[i];
    ((__half2*)hi)[2*i]   = __halves2half2(__float2half(v.x), __float2half(v.y));
    ((__half2*)hi)[2*i+1] = __halves2half2(__float2half(v.z), __float2half(v.w));
}

__global__ __launch_bounds__(256)
void conv_w(const float* __restrict__ wa, const float* __restrict__ wb,
            const float* __restrict__ wc, __half* __restrict__ dst){
    const size_t n0 = (size_t)2304*KDIM/4;
    const size_t n1 = (size_t)768*KDIM/4;
    const size_t n2 = (size_t)384*KDIM/4;
    size_t i = (size_t)blockIdx.x * blockDim.x + threadIdx.x;
    if (i >= n0 + n1 + n2) return;
    const float* src; size_t off;
    if (i < n0){ src = wa; off = i; }
    else if (i < n0 + n1){ src = wb; off = i - n0; }
    else { src = wc; off = i - n0 - n1; }
    float4 v = ((const float4*)src)[off];
    ((__half2*)dst)[2*i]   = __halves2half2(__float2half(v.x), __float2half(v.y));
    ((__half2*)dst)[2*i+1] = __halves2half2(__float2half(v.z), __float2half(v.w));
}

// ---------------- 1-pass GEMM: C = A @ B^T + bias -> fp16, BK=64 -----------
__global__ __launch_bounds__(256, 2)
void gemm_1p(const __half* __restrict__ Ahi, const __half* __restrict__ Bhi,
             const float* __restrict__ bias, __half* __restrict__ Chi, int N)
{
    extern __shared__ __align__(1024) char sm[];
    constexpr uint32_t STGB = 32768u;
    const int tid = threadIdx.x, lane = tid & 31, warp = tid >> 5;
    const int m0 = blockIdx.y * 128, n0 = blockIdx.x * 128;
    const int wm = (warp & 1) * 64, wn = (warp >> 1) * 32;
    const uint32_t sbase = s2u(sm);

    auto load_tile = [&](int t){
        const uint32_t st = sbase + (uint32_t)(t % 3) * STGB;
        const int k0 = t * 64;
        #pragma unroll
        for (int i = 0; i < 4; i++){
            int g = tid + i * 256;
            int row = g >> 3, gg = g & 7;
            uint32_t d = SWZ((uint32_t)(row * 128 + gg * 16));
            CP16(st + d, Ahi + (size_t)(m0 + row) * KDIM + k0 + gg * 8);
        }
        #pragma unroll
        for (int i = 0; i < 4; i++){
            int g = tid + i * 256;
            int row = g >> 3, gg = g & 7;
            uint32_t d = SWZ((uint32_t)(row * 128 + gg * 16));
            CP16(st + 16384u + d, Bhi + (size_t)(n0 + row) * KDIM + k0 + gg * 8);
        }
        asm volatile("cp.async.commit_group;" ::: "memory");
    };

    float acc[4][4][4];
    #pragma unroll
    for (int mi = 0; mi < 4; mi++)
        #pragma unroll
        for (int ni = 0; ni < 4; ni++)
            #pragma unroll
            for (int r = 0; r < 4; r++) acc[mi][ni][r] = 0.0f;

    load_tile(0);
    load_tile(1);

    const uint32_t aRow = (uint32_t)(lane & 15);
    const uint32_t aCol = (uint32_t)(lane >> 4) * 16u;
    const uint32_t bRow = (uint32_t)(((lane >> 4) & 1) * 8 + (lane & 7));
    const uint32_t bCol = (uint32_t)((lane >> 3) & 1) * 16u;

    #pragma unroll 1
    for (int t = 0; t < NCH1; t++){
        if (t < NCH1 - 1) asm volatile("cp.async.wait_group 1;" ::: "memory");
        else              asm volatile("cp.async.wait_group 0;" ::: "memory");
        __syncthreads();
        if (t + 2 < NCH1) load_tile(t + 2);

        const uint32_t sA = sbase + (uint32_t)(t % 3) * STGB;
        const uint32_t sB = sA + 16384u;

        #pragma unroll
        for (int kk = 0; kk < 4; kk++){
            const uint32_t kb = (uint32_t)kk * 32u;
            uint32_t a[4][4], bh[8];
            #pragma unroll
            for (int np = 0; np < 2; np++){
                uint32_t ad = sB + SWZ((uint32_t)((wn + np*16 + bRow) * 128) + kb + bCol);
                asm volatile("ldmatrix.sync.aligned.m8n8.x4.shared.b16 {%0,%1,%2,%3},[%4];"
                    : "=r"(bh[np*4]), "=r"(bh[np*4+1]), "=r"(bh[np*4+2]), "=r"(bh[np*4+3]) : "r"(ad));
            }
            #pragma unroll
            for (int mi = 0; mi < 4; mi++){
                uint32_t ad = sA + SWZ((uint32_t)((wm + mi*16 + aRow) * 128) + kb + aCol);
                asm volatile("ldmatrix.sync.aligned.m8n8.x4.shared.b16 {%0,%1,%2,%3},[%4];"
                    : "=r"(a[mi][0]), "=r"(a[mi][1]), "=r"(a[mi][2]), "=r"(a[mi][3]) : "r"(ad));
            }
            #pragma unroll
            for (int mi = 0; mi < 4; mi++)
                #pragma unroll
                for (int ni = 0; ni < 4; ni++)
                    mma16816(acc[mi][ni], a[mi], bh[(ni>>1)*4 + (ni&1)*2], bh[(ni>>1)*4 + (ni&1)*2 + 1]);
        }
    }

    const int erow = lane >> 2;
    const int ecol = (lane & 3) * 2;
    #pragma unroll
    for (int mi = 0; mi < 4; mi++){
        #pragma unroll
        for (int ni = 0; ni < 4; ni++){
            const int row = m0 + wm + mi * 16 + erow;
            const int col = n0 + wn + ni * 8 + ecol;
            const float b0 = bias[col], b1 = bias[col + 1];
            float v0 = acc[mi][ni][0] + b0, v1 = acc[mi][ni][1] + b1;
            float v2 = acc[mi][ni][2] + b0, v3 = acc[mi][ni][3] + b1;
            *(__half2*)(Chi + (size_t)row * N + col)
                = __halves2half2(__float2half(v0), __float2half(v1));
            *(__half2*)(Chi + (size_t)(row + 8) * N + col)
                = __halves2half2(__float2half(v2), __float2half(v3));
        }
    }
}

// ---------------- fused MLP: 1-pass BK=64, epilogue dots w2 -----------------
__global__ __launch_bounds__(256, 2)
void gemm_fused(const __half* __restrict__ Ahi, const __half* __restrict__ Bhi,
                const float* __restrict__ bias, const float* __restrict__ w2,
                float* __restrict__ part)
{
    extern __shared__ __align__(1024) char sm[];
    constexpr uint32_t STGB = 32768u;
    const int tid = threadIdx.x, lane = tid & 31, warp = tid >> 5;
    const int m0 = blockIdx.y * 128, n0 = blockIdx.x * 128;
    const int wm = (warp & 1) * 64, wn = (warp >> 1) * 32;
    const uint32_t sbase = s2u(sm);

    auto load_tile = [&](int t){
        const uint32_t st = sbase + (uint32_t)(t % 3) * STGB;
        const int k0 = t * 64;
        #pragma unroll
        for (int i = 0; i < 4; i++){
            int g = tid + i * 256;
            int row = g >> 3, gg = g & 7;
            uint32_t d = SWZ((uint32_t)(row * 128 + gg * 16));
            CP16(st + d, Ahi + (size_t)(m0 + row) * KDIM + k0 + gg * 8);
        }
        #pragma unroll
        for (int i = 0; i < 4; i++){
            int g = tid + i * 256;
            int row = g >> 3, gg = g & 7;
            uint32_t d = SWZ((uint32_t)(row * 128 + gg * 16));
            CP16(st + 16384u + d, Bhi + (size_t)(n0 + row) * KDIM + k0 + gg * 8);
        }
        asm volatile("cp.async.commit_group;" ::: "memory");
    };

    float acc[4][4][4];
    #pragma unroll
    for (int mi = 0; mi < 4; mi++)
        #pragma unroll
        for (int ni = 0; ni < 4; ni++)
            #pragma unroll
            for (int r = 0; r < 4; r++) acc[mi][ni][r] = 0.0f;

    load_tile(0);
    load_tile(1);

    const uint32_t aRow = (uint32_t)(lane & 15);
    const uint32_t aCol = (uint32_t)(lane >> 4) * 16u;
    const uint32_t bRow = (uint32_t)(((lane >> 4) & 1) * 8 + (lane & 7));
    const uint32_t bCol = (uint32_t)((lane >> 3) & 1) * 16u;

    #pragma unroll 1
    for (int t = 0; t < NCH1; t++){
        if (t < NCH1 - 1) asm volatile("cp.async.wait_group 1;" ::: "memory");
        else              asm volatile("cp.async.wait_group 0;" ::: "memory");
        __syncthreads();
        if (t + 2 < NCH1) load_tile(t + 2);

        const uint32_t sA = sbase + (uint32_t)(t % 3) * STGB;
        const uint32_t sB = sA + 16384u;

        #pragma unroll
        for (int kk = 0; kk < 4; kk++){
            const uint32_t kb = (uint32_t)kk * 32u;
            uint32_t a[4][4], bh[8];
            #pragma unroll
            for (int np = 0; np < 2; np++){
                uint32_t ad = sB + SWZ((uint32_t)((wn + np*16 + bRow) * 128) + kb + bCol);
                asm volatile("ldmatrix.sync.aligned.m8n8.x4.shared.b16 {%0,%1,%2,%3},[%4];"
                    : "=r"(bh[np*4]), "=r"(bh[np*4+1]), "=r"(bh[np*4+2]), "=r"(bh[np*4+3]) : "r"(ad));
            }
            #pragma unroll
            for (int mi = 0; mi < 4; mi++){
                uint32_t ad = sA + SWZ((uint32_t)((wm + mi*16 + aRow) * 128) + kb + aCol);
                asm volatile("ldmatrix.sync.aligned.m8n8.x4.shared.b16 {%0,%1,%2,%3},[%4];"
                    : "=r"(a[mi][0]), "=r"(a[mi][1]), "=r"(a[mi][2]), "=r"(a[mi][3]) : "r"(ad));
            }
            #pragma unroll
            for (int mi = 0; mi < 4; mi++)
                #pragma unroll
                for (int ni = 0; ni < 4; ni++)
                    mma16816(acc[mi][ni], a[mi], bh[(ni>>1)*4 + (ni&1)*2], bh[(ni>>1)*4 + (ni&1)*2 + 1]);
        }
    }

    const int erow = lane >> 2;
    const int ecol = (lane & 3) * 2;
    const int slot = blockIdx.x * 4 + (warp >> 1);
    #pragma unroll
    for (int mi = 0; mi < 4; mi++){
        float rs0 = 0.f, rs1 = 0.f;
        #pragma unroll
        for (int ni = 0; ni < 4; ni++){
            const int col = n0 + wn + ni * 8 + ecol;
            const float b0 = bias[col], b1 = bias[col + 1];
            const float w0 = w2[col],   w1 = w2[col + 1];
            rs0 += fmaxf(acc[mi][ni][0] + b0, 0.f) * w0
                 + fmaxf(acc[mi][ni][1] + b1, 0.f) * w1;
            rs1 += fmaxf(acc[mi][ni][2] + b0, 0.f) * w0
                 + fmaxf(acc[mi][ni][3] + b1, 0.f) * w1;
        }
        rs0 += __shfl_xor_sync(0xFFFFFFFFu, rs0, 1);
        rs0 += __shfl_xor_sync(0xFFFFFFFFu, rs0, 2);
        rs1 += __shfl_xor_sync(0xFFFFFFFFu, rs1, 1);
        rs1 += __shfl_xor_sync(0xFFFFFFFFu, rs1, 2);
        if ((lane & 3) == 0){
            const int row = m0 + wm + mi * 16 + erow;
            part[(size_t)row * 12 + slot]       = rs0;
            part[(size_t)(row + 8) * 12 + slot] = rs1;
        }
    }
}

// ---------------- attention: tensor-core, one warp per head -----------------
// Block per s: coalesced load of 16x2304 fp16 into smem; warp h computes
// scores (mma), softmax in registers (quad shfl), P packed fragment-to-
// fragment (C layout == A layout), PV (mma with ldmatrix.trans V).
__global__ __launch_bounds__(256)
void attn_kernel(){
    extern __shared__ __align__(16) char smraw[];
    __half* buf = (__half*)smraw;                    // [16][ASTRIDE]
    const int s = blockIdx.x, tid = threadIdx.x;
    const int h = tid >> 5, lane = tid & 31;

    for (int c = tid; c < 4608; c += 256){
        int l = c / 288, cc = c - l * 288;
        const __half* src = g_qkvh + (size_t)l * ((size_t)SSEQ * 2304)
                          + (size_t)s * 2304 + cc * 8;
        *(uint4*)(buf + l * ASTRIDE + cc * 8) = *(const uint4*)src;
    }
    __syncthreads();

    const uint32_t sb = s2u(buf);
    const uint32_t qRow = (uint32_t)(lane & 15);
    const uint32_t qSel = (uint32_t)(lane >> 4) * 8u;               // +8 halves
    const uint32_t kRow = (uint32_t)(((lane >> 4) & 1) * 8 + (lane & 7));
    const uint32_t kSel = (uint32_t)((lane >> 3) & 1) * 8u;

    // ---- scores: Q @ K^T, 6 k-chunks of 16 ----
    float ct0[4] = {0,0,0,0}, ct1[4] = {0,0,0,0};
    #pragma unroll
    for (int kc = 0; kc < 6; kc++){
        uint32_t a[4], b[4];
        uint32_t qa = sb + 2u * (qRow * ASTRIDE + (uint32_t)(h * 96 + kc * 16) + qSel);
        asm volatile("ldmatrix.sync.aligned.m8n8.x4.shared.b16 {%0,%1,%2,%3},[%4];"
            : "=r"(a[0]), "=r"(a[1]), "=r"(a[2]), "=r"(a[3]) : "r"(qa));
        uint32_t ka = sb + 2u * (kRow * ASTRIDE + (uint32_t)(768 + h * 96 + kc * 16) + kSel);
        asm volatile("ldmatrix.sync.aligned.m8n8.x4.shared.b16 {%0,%1,%2,%3},[%4];"
            : "=r"(b[0]), "=r"(b[1]), "=r"(b[2]), "=r"(b[3]) : "r"(ka));
        mma16816(ct0, a, b[0], b[1]);   // K rows 0-7
        mma16816(ct1, a, b[2], b[3]);   // K rows 8-15
    }

    // ---- softmax in registers ----
    const float scale = rsqrtf((float)DHEAD);
    float rA0 = ct0[0]*scale, rA1 = ct0[1]*scale, rA2 = ct1[0]*scale, rA3 = ct1[1]*scale;
    float rB0 = ct0[2]*scale, rB1 = ct0[3]*scale, rB2 = ct1[2]*scale, rB3 = ct1[3]*scale;

    float mxA = fmaxf(fmaxf(rA0, rA1), fmaxf(rA2, rA3));
    mxA = fmaxf(mxA, __shfl_xor_sync(0xFFFFFFFFu, mxA, 1));
    mxA = fmaxf(mxA, __shfl_xor_sync(0xFFFFFFFFu, mxA, 2));
    float mxB = fmaxf(fmaxf(rB0, rB1), fmaxf(rB2, rB3));
    mxB = fmaxf(mxB, __shfl_xor_sync(0xFFFFFFFFu, mxB, 1));
    mxB = fmaxf(mxB, __shfl_xor_sync(0xFFFFFFFFu, mxB, 2));

    rA0 = __expf(rA0 - mxA); rA1 = __expf(rA1 - mxA);
    rA2 = __expf(rA2 - mxA); rA3 = __expf(rA3 - mxA);
    rB0 = __expf(rB0 - mxB); rB1 = __expf(rB1 - mxB);
    rB2 = __expf(rB2 - mxB); rB3 = __expf(rB3 - mxB);

    float smA = rA0 + rA1 + rA2 + rA3;
    smA += __shfl_xor_sync(0xFFFFFFFFu, smA, 1);
    smA += __shfl_xor_sync(0xFFFFFFFFu, smA, 2);
    float smB = rB0 + rB1 + rB2 + rB3;
    smB += __shfl_xor_sync(0xFFFFFFFFu, smB, 1);
    smB += __shfl_xor_sync(0xFFFFFFFFu, smB, 2);
    const float ivA = 1.f / smA, ivB = 1.f / smB;

    // ---- pack P fragments (C layout == A layout) ----
    uint32_t p[4];
    __half2 h2;
    h2 = __halves2half2(__float2half(rA0*ivA), __float2half(rA1*ivA)); p[0] = *(uint32_t*)&h2;
    h2 = __halves2half2(__float2half(rB0*ivB), __float2half(rB1*ivB)); p[1] = *(uint32_t*)&h2;
    h2 = __halves2half2(__float2half(rA2*ivA), __float2half(rA3*ivA)); p[2] = *(uint32_t*)&h2;
    h2 = __halves2half2(__float2half(rB2*ivB), __float2half(rB3*ivB)); p[3] = *(uint32_t*)&h2;

    // ---- PV: P(16x16) @ V(16x96), 12 n-chunks of 8 ----
    const uint32_t vRow = (uint32_t)(lane & 15);
    const int erow = lane >> 2;
    const int ecol = (lane & 3) * 2;
    #pragma unroll
    for (int j = 0; j < 12; j++){
        uint32_t vb[2];
        uint32_t va = sb + 2u * (vRow * ASTRIDE + (uint32_t)(1536 + h * 96 + j * 8));
        asm volatile("ldmatrix.sync.aligned.m8n8.x2.trans.shared.b16 {%0,%1},[%2];"
            : "=r"(vb[0]), "=r"(vb[1]) : "r"(va));
        float o[4] = {0,0,0,0};
        mma16816(o, p, vb[0], vb[1]);
        size_t o0 = ((size_t)erow * SSEQ + s) * EMB + h * 96 + j * 8 + ecol;
        *(__half2*)(g_chi + o0)
            = __halves2half2(__float2half(o[0]), __float2half(o[1]));
        *(__half2*)(g_chi + o0 + (size_t)8 * SSEQ * EMB)
            = __halves2half2(__float2half(o[2]), __float2half(o[3]));
    }
}

// ---------------- broadcast: out[r,:] = sum(part[r]) + b2 -------------------
__global__ __launch_bounds__(256)
void bcast(const float* __restrict__ part, const float* __restrict__ b2,
           float* __restrict__ out){
    const int r = blockIdx.x * 2 + (threadIdx.x >> 7);
    const int t = threadIdx.x & 127;
    float p = b2[0];
    #pragma unroll
    for (int s = 0; s < 12; s++) p += part[(size_t)r * 12 + s];
    float4 p4 = make_float4(p, p, p, p);
    float4* orow = (float4*)(out + (size_t)r * SSEQ);
    #pragma unroll
    for (int i = 0; i < 4; i++) orow[t + i*128] = p4;
}

// ---------------------------------------------------------------------------
extern "C" void kernel_launch(void* const* d_in, const int* in_sizes, int n_in,
                              void* d_out, int out_size){
    const float* features = (const float*)d_in[0];
    const float* in_w  = (const float*)d_in[1];
    const float* in_b  = (const float*)d_in[2];
    const float* out_w = (const float*)d_in[3];
    const float* out_b = (const float*)d_in[4];
    const float* w1    = (const float*)d_in[5];
    const float* b1    = (const float*)d_in[6];
    const float* w2    = (const float*)d_in[7];
    const float* b2    = (const float*)d_in[8];
    float* out = (float*)d_out;

    float *pt;
    __half *qkvh,*fhi,*chi,*ohi,*whi;
    cudaGetSymbolAddress((void**)&qkvh, g_qkvh);
    cudaGetSymbolAddress((void**)&pt,  g_part);
    cudaGetSymbolAddress((void**)&fhi, g_fhi);
    cudaGetSymbolAddress((void**)&chi, g_chi);
    cudaGetSymbolAddress((void**)&ohi, g_ohi);
    cudaGetSymbolAddress((void**)&whi, g_whi);

    const size_t OFF_OW = (size_t)2304*KDIM;
    const size_t OFF_W1 = (size_t)(2304+768)*KDIM;

    const int SMEM1 = 3 * 32768;
    const int SMEMA = 16 * ASTRIDE * 2;        // 73984 B
    cudaFuncSetAttribute(gemm_1p,    cudaFuncAttributeMaxDynamicSharedMemorySize, SMEM1);
    cudaFuncSetAttribute(gemm_fused, cudaFuncAttributeMaxDynamicSharedMemorySize, SMEM1);
    cudaFuncSetAttribute(attn_kernel, cudaFuncAttributeMaxDynamicSharedMemorySize, SMEMA);

    // 1-2) converts
    {
        size_t n4 = (size_t)MROWS*KDIM/4;
        conv4<<<(unsigned)((n4+255)/256), 256>>>(features, fhi, n4);
        size_t nw4 = (size_t)(2304+768+384)*KDIM/4;
        conv_w<<<(unsigned)((nw4+255)/256), 256>>>(in_w, out_w, w1, whi);
    }

    // 3) QKV = features @ in_w^T + in_b  -> fp16
    gemm_1p<<<dim3(2304/128, MROWS/128), 256, SMEM1>>>(
        fhi, whi, in_b, qkvh, 2304);

    // 4) attention (profiled slot) -> ctx fp16, tensor-core path
    attn_kernel<<<SSEQ, 256, SMEMA>>>();

    // 5) att = ctx @ out_w^T + out_b -> fp16
    gemm_1p<<<dim3(768/128, MROWS/128), 256, SMEM1>>>(
        chi, whi+OFF_OW, out_b, ohi, 768);

    // 6) fused MLP -> 12 partials/row
    gemm_fused<<<dim3(384/128, MROWS/128), 256, SMEM1>>>(
        ohi, whi+OFF_W1, b1, w2, pt);

    // 7) broadcast
    bcast<<<MROWS/2, 256>>>(pt, b2, out);
}

// round 15
// speedup vs baseline: 1.2761x; 1.0125x over previous
#include <cuda_runtime.h>
#include <cuda_fp16.h>
#include <math.h>
#include <stdint.h>

#define BBATCH 16
#define SSEQ   2048
#define EMB    768
#define NHEAD  8
#define DHEAD  96
#define MROWS  (BBATCH*SSEQ)   // 32768
#define KDIM   768
#define NCH1   12              // 768 / 64  (1-pass, BK=64)
#define ASTRIDE 2312           // attn smem row stride (halves)

// ---------------- scratch (device globals; allocation-free rule) -----------
__device__ __half  g_qkvh[(size_t)MROWS*2304];
__device__ __half  g_fhi[(size_t)MROWS*KDIM];
__device__ __half  g_chi[(size_t)MROWS*KDIM];
__device__ __half  g_ohi[(size_t)MROWS*KDIM];
__device__ float   g_part[(size_t)MROWS*12];
__device__ __half  g_whi[(size_t)(2304+768+384)*KDIM];

// ---------------- helpers ---------------------------------------------------
__device__ __forceinline__ uint32_t s2u(const void* p){
    uint32_t a;
    asm("{ .reg .u64 t; cvta.to.shared.u64 t, %1; cvt.u32.u64 %0, t; }":"=r"(a):"l"(p));
    return a;
}
#define SWZ(o)   ((o) ^ (((o) >> 3) & 0x70))
#define CP16(s, g) asm volatile("cp.async.cg.shared.global [%0], [%1], 16;"::"r"(s),"l"(g):"memory")

__device__ __forceinline__ void mma16816(float* c, const uint32_t* a, uint32_t b0, uint32_t b1){
    asm volatile("mma.sync.aligned.m16n8k16.row.col.f32.f16.f16.f32 "
        "{%0,%1,%2,%3},{%4,%5,%6,%7},{%8,%9},{%0,%1,%2,%3};"
        : "+f"(c[0]), "+f"(c[1]), "+f"(c[2]), "+f"(c[3])
        : "r"(a[0]), "r"(a[1]), "r"(a[2]), "r"(a[3]), "r"(b0), "r"(b1));
}

// ---------------- fp32 -> fp16 converts -------------------------------------
__global__ __launch_bounds__(256)
void conv4(const float* __restrict__ src, __half* __restrict__ hi, size_t n4){
    size_t i = (size_t)blockIdx.x * blockDim.x + threadIdx.x;
    if (i >= n4) return;
    float4 v = ((const float4*)src)[i];
    ((__half2*)hi)[2*i]   = __halves2half2(__float2half(v.x), __float2half(v.y));
    ((__half2*)hi)[2*i+1] = __halves2half2(__float2half(v.z), __float2half(v.w));
}

__global__ __launch_bounds__(256)
void conv_w(const float* __restrict__ wa, const float* __restrict__ wb,
            const float* __restrict__ wc, __half* __restrict__ dst){
    const size_t n0 = (size_t)2304*KDIM/4;
    const size_t n1 = (size_t)768*KDIM/4;
    const size_t n2 = (size_t)384*KDIM/4;
    size_t i = (size_t)blockIdx.x * blockDim.x + threadIdx.x;
    if (i >= n0 + n1 + n2) return;
    const float* src; size_t off;
    if (i < n0){ src = wa; off = i; }
    else if (i < n0 + n1){ src = wb; off = i - n0; }
    else { src = wc; off = i - n0 - n1; }
    float4 v = ((const float4*)src)[off];
    ((__half2*)dst)[2*i]   = __halves2half2(__float2half(v.x), __float2half(v.y));
    ((__half2*)dst)[2*i+1] = __halves2half2(__float2half(v.z), __float2half(v.w));
}

// ---------------- 1-pass GEMM: C = A @ B^T + bias -> fp16, BK=64 -----------
__global__ __launch_bounds__(256, 2)
void gemm_1p(const __half* __restrict__ Ahi, const __half* __restrict__ Bhi,
             const float* __restrict__ bias, __half* __restrict__ Chi, int N)
{
    extern __shared__ __align__(1024) char sm[];
    constexpr uint32_t STGB = 32768u;
    const int tid = threadIdx.x, lane = tid & 31, warp = tid >> 5;
    const int m0 = blockIdx.y * 128, n0 = blockIdx.x * 128;
    const int wm = (warp & 1) * 64, wn = (warp >> 1) * 32;
    const uint32_t sbase = s2u(sm);

    auto load_tile = [&](int t){
        const uint32_t st = sbase + (uint32_t)(t % 3) * STGB;
        const int k0 = t * 64;
        #pragma unroll
        for (int i = 0; i < 4; i++){
            int g = tid + i * 256;
            int row = g >> 3, gg = g & 7;
            uint32_t d = SWZ((uint32_t)(row * 128 + gg * 16));
            CP16(st + d, Ahi + (size_t)(m0 + row) * KDIM + k0 + gg * 8);
        }
        #pragma unroll
        for (int i = 0; i < 4; i++){
            int g = tid + i * 256;
            int row = g >> 3, gg = g & 7;
            uint32_t d = SWZ((uint32_t)(row * 128 + gg * 16));
            CP16(st + 16384u + d, Bhi + (size_t)(n0 + row) * KDIM + k0 + gg * 8);
        }
        asm volatile("cp.async.commit_group;" ::: "memory");
    };

    float acc[4][4][4];
    #pragma unroll
    for (int mi = 0; mi < 4; mi++)
        #pragma unroll
        for (int ni = 0; ni < 4; ni++)
            #pragma unroll
            for (int r = 0; r < 4; r++) acc[mi][ni][r] = 0.0f;

    load_tile(0);
    load_tile(1);

    const uint32_t aRow = (uint32_t)(lane & 15);
    const uint32_t aCol = (uint32_t)(lane >> 4) * 16u;
    const uint32_t bRow = (uint32_t)(((lane >> 4) & 1) * 8 + (lane & 7));
    const uint32_t bCol = (uint32_t)((lane >> 3) & 1) * 16u;

    #pragma unroll 1
    for (int t = 0; t < NCH1; t++){
        if (t < NCH1 - 1) asm volatile("cp.async.wait_group 1;" ::: "memory");
        else              asm volatile("cp.async.wait_group 0;" ::: "memory");
        __syncthreads();
        if (t + 2 < NCH1) load_tile(t + 2);

        const uint32_t sA = sbase + (uint32_t)(t % 3) * STGB;
        const uint32_t sB = sA + 16384u;

        #pragma unroll
        for (int kk = 0; kk < 4; kk++){
            const uint32_t kb = (uint32_t)kk * 32u;
            uint32_t a[4][4], bh[8];
            #pragma unroll
            for (int np = 0; np < 2; np++){
                uint32_t ad = sB + SWZ((uint32_t)((wn + np*16 + bRow) * 128) + kb + bCol);
                asm volatile("ldmatrix.sync.aligned.m8n8.x4.shared.b16 {%0,%1,%2,%3},[%4];"
                    : "=r"(bh[np*4]), "=r"(bh[np*4+1]), "=r"(bh[np*4+2]), "=r"(bh[np*4+3]) : "r"(ad));
            }
            #pragma unroll
            for (int mi = 0; mi < 4; mi++){
                uint32_t ad = sA + SWZ((uint32_t)((wm + mi*16 + aRow) * 128) + kb + aCol);
                asm volatile("ldmatrix.sync.aligned.m8n8.x4.shared.b16 {%0,%1,%2,%3},[%4];"
                    : "=r"(a[mi][0]), "=r"(a[mi][1]), "=r"(a[mi][2]), "=r"(a[mi][3]) : "r"(ad));
            }
            #pragma unroll
            for (int mi = 0; mi < 4; mi++)
                #pragma unroll
                for (int ni = 0; ni < 4; ni++)
                    mma16816(acc[mi][ni], a[mi], bh[(ni>>1)*4 + (ni&1)*2], bh[(ni>>1)*4 + (ni&1)*2 + 1]);
        }
    }

    const int erow = lane >> 2;
    const int ecol = (lane & 3) * 2;
    #pragma unroll
    for (int mi = 0; mi < 4; mi++){
        #pragma unroll
        for (int ni = 0; ni < 4; ni++){
            const int row = m0 + wm + mi * 16 + erow;
            const int col = n0 + wn + ni * 8 + ecol;
            const float b0 = bias[col], b1 = bias[col + 1];
            float v0 = acc[mi][ni][0] + b0, v1 = acc[mi][ni][1] + b1;
            float v2 = acc[mi][ni][2] + b0, v3 = acc[mi][ni][3] + b1;
            *(__half2*)(Chi + (size_t)row * N + col)
                = __halves2half2(__float2half(v0), __float2half(v1));
            *(__half2*)(Chi + (size_t)(row + 8) * N + col)
                = __halves2half2(__float2half(v2), __float2half(v3));
        }
    }
}

// ---------------- fused MLP: 1-pass BK=64, epilogue dots w2 -----------------
__global__ __launch_bounds__(256, 2)
void gemm_fused(const __half* __restrict__ Ahi, const __half* __restrict__ Bhi,
                const float* __restrict__ bias, const float* __restrict__ w2,
                float* __restrict__ part)
{
    extern __shared__ __align__(1024) char sm[];
    constexpr uint32_t STGB = 32768u;
    const int tid = threadIdx.x, lane = tid & 31, warp = tid >> 5;
    const int m0 = blockIdx.y * 128, n0 = blockIdx.x * 128;
    const int wm = (warp & 1) * 64, wn = (warp >> 1) * 32;
    const uint32_t sbase = s2u(sm);

    auto load_tile = [&](int t){
        const uint32_t st = sbase + (uint32_t)(t % 3) * STGB;
        const int k0 = t * 64;
        #pragma unroll
        for (int i = 0; i < 4; i++){
            int g = tid + i * 256;
            int row = g >> 3, gg = g & 7;
            uint32_t d = SWZ((uint32_t)(row * 128 + gg * 16));
            CP16(st + d, Ahi + (size_t)(m0 + row) * KDIM + k0 + gg * 8);
        }
        #pragma unroll
        for (int i = 0; i < 4; i++){
            int g = tid + i * 256;
            int row = g >> 3, gg = g & 7;
            uint32_t d = SWZ((uint32_t)(row * 128 + gg * 16));
            CP16(st + 16384u + d, Bhi + (size_t)(n0 + row) * KDIM + k0 + gg * 8);
        }
        asm volatile("cp.async.commit_group;" ::: "memory");
    };

    float acc[4][4][4];
    #pragma unroll
    for (int mi = 0; mi < 4; mi++)
        #pragma unroll
        for (int ni = 0; ni < 4; ni++)
            #pragma unroll
            for (int r = 0; r < 4; r++) acc[mi][ni][r] = 0.0f;

    load_tile(0);
    load_tile(1);

    const uint32_t aRow = (uint32_t)(lane & 15);
    const uint32_t aCol = (uint32_t)(lane >> 4) * 16u;
    const uint32_t bRow = (uint32_t)(((lane >> 4) & 1) * 8 + (lane & 7));
    const uint32_t bCol = (uint32_t)((lane >> 3) & 1) * 16u;

    #pragma unroll 1
    for (int t = 0; t < NCH1; t++){
        if (t < NCH1 - 1) asm volatile("cp.async.wait_group 1;" ::: "memory");
        else              asm volatile("cp.async.wait_group 0;" ::: "memory");
        __syncthreads();
        if (t + 2 < NCH1) load_tile(t + 2);

        const uint32_t sA = sbase + (uint32_t)(t % 3) * STGB;
        const uint32_t sB = sA + 16384u;

        #pragma unroll
        for (int kk = 0; kk < 4; kk++){
            const uint32_t kb = (uint32_t)kk * 32u;
            uint32_t a[4][4], bh[8];
            #pragma unroll
            for (int np = 0; np < 2; np++){
                uint32_t ad = sB + SWZ((uint32_t)((wn + np*16 + bRow) * 128) + kb + bCol);
                asm volatile("ldmatrix.sync.aligned.m8n8.x4.shared.b16 {%0,%1,%2,%3},[%4];"
                    : "=r"(bh[np*4]), "=r"(bh[np*4+1]), "=r"(bh[np*4+2]), "=r"(bh[np*4+3]) : "r"(ad));
            }
            #pragma unroll
            for (int mi = 0; mi < 4; mi++){
                uint32_t ad = sA + SWZ((uint32_t)((wm + mi*16 + aRow) * 128) + kb + aCol);
                asm volatile("ldmatrix.sync.aligned.m8n8.x4.shared.b16 {%0,%1,%2,%3},[%4];"
                    : "=r"(a[mi][0]), "=r"(a[mi][1]), "=r"(a[mi][2]), "=r"(a[mi][3]) : "r"(ad));
            }
            #pragma unroll
            for (int mi = 0; mi < 4; mi++)
                #pragma unroll
                for (int ni = 0; ni < 4; ni++)
                    mma16816(acc[mi][ni], a[mi], bh[(ni>>1)*4 + (ni&1)*2], bh[(ni>>1)*4 + (ni&1)*2 + 1]);
        }
    }

    const int erow = lane >> 2;
    const int ecol = (lane & 3) * 2;
    const int slot = blockIdx.x * 4 + (warp >> 1);
    #pragma unroll
    for (int mi = 0; mi < 4; mi++){
        float rs0 = 0.f, rs1 = 0.f;
        #pragma unroll
        for (int ni = 0; ni < 4; ni++){
            const int col = n0 + wn + ni * 8 + ecol;
            const float b0 = bias[col], b1 = bias[col + 1];
            const float w0 = w2[col],   w1 = w2[col + 1];
            rs0 += fmaxf(acc[mi][ni][0] + b0, 0.f) * w0
                 + fmaxf(acc[mi][ni][1] + b1, 0.f) * w1;
            rs1 += fmaxf(acc[mi][ni][2] + b0, 0.f) * w0
                 + fmaxf(acc[mi][ni][3] + b1, 0.f) * w1;
        }
        rs0 += __shfl_xor_sync(0xFFFFFFFFu, rs0, 1);
        rs0 += __shfl_xor_sync(0xFFFFFFFFu, rs0, 2);
        rs1 += __shfl_xor_sync(0xFFFFFFFFu, rs1, 1);
        rs1 += __shfl_xor_sync(0xFFFFFFFFu, rs1, 2);
        if ((lane & 3) == 0){
            const int row = m0 + wm + mi * 16 + erow;
            part[(size_t)row * 12 + slot]       = rs0;
            part[(size_t)(row + 8) * 12 + slot] = rs1;
        }
    }
}

// ---------------- attention: tensor-core, smem-staged coalesced output ------
// Warp h overwrites its own dead Q region with ctx, then the block stores
// 16 rows x 1.5KB fully coalesced.
__global__ __launch_bounds__(256)
void attn_kernel(){
    extern __shared__ __align__(16) char smraw[];
    __half* buf = (__half*)smraw;                    // [16][ASTRIDE]
    const int s = blockIdx.x, tid = threadIdx.x;
    const int h = tid >> 5, lane = tid & 31;

    for (int c = tid; c < 4608; c += 256){
        int l = c / 288, cc = c - l * 288;
        const __half* src = g_qkvh + (size_t)l * ((size_t)SSEQ * 2304)
                          + (size_t)s * 2304 + cc * 8;
        *(uint4*)(buf + l * ASTRIDE + cc * 8) = *(const uint4*)src;
    }
    __syncthreads();

    const uint32_t sb = s2u(buf);
    const uint32_t qRow = (uint32_t)(lane & 15);
    const uint32_t qSel = (uint32_t)(lane >> 4) * 8u;
    const uint32_t kRow = (uint32_t)(((lane >> 4) & 1) * 8 + (lane & 7));
    const uint32_t kSel = (uint32_t)((lane >> 3) & 1) * 8u;

    // ---- scores: Q @ K^T, 6 k-chunks of 16 ----
    float ct0[4] = {0,0,0,0}, ct1[4] = {0,0,0,0};
    #pragma unroll
    for (int kc = 0; kc < 6; kc++){
        uint32_t a[4], b[4];
        uint32_t qa = sb + 2u * (qRow * ASTRIDE + (uint32_t)(h * 96 + kc * 16) + qSel);
        asm volatile("ldmatrix.sync.aligned.m8n8.x4.shared.b16 {%0,%1,%2,%3},[%4];"
            : "=r"(a[0]), "=r"(a[1]), "=r"(a[2]), "=r"(a[3]) : "r"(qa));
        uint32_t ka = sb + 2u * (kRow * ASTRIDE + (uint32_t)(768 + h * 96 + kc * 16) + kSel);
        asm volatile("ldmatrix.sync.aligned.m8n8.x4.shared.b16 {%0,%1,%2,%3},[%4];"
            : "=r"(b[0]), "=r"(b[1]), "=r"(b[2]), "=r"(b[3]) : "r"(ka));
        mma16816(ct0, a, b[0], b[1]);
        mma16816(ct1, a, b[2], b[3]);
    }

    // ---- softmax in registers ----
    const float scale = rsqrtf((float)DHEAD);
    float rA0 = ct0[0]*scale, rA1 = ct0[1]*scale, rA2 = ct1[0]*scale, rA3 = ct1[1]*scale;
    float rB0 = ct0[2]*scale, rB1 = ct0[3]*scale, rB2 = ct1[2]*scale, rB3 = ct1[3]*scale;

    float mxA = fmaxf(fmaxf(rA0, rA1), fmaxf(rA2, rA3));
    mxA = fmaxf(mxA, __shfl_xor_sync(0xFFFFFFFFu, mxA, 1));
    mxA = fmaxf(mxA, __shfl_xor_sync(0xFFFFFFFFu, mxA, 2));
    float mxB = fmaxf(fmaxf(rB0, rB1), fmaxf(rB2, rB3));
    mxB = fmaxf(mxB, __shfl_xor_sync(0xFFFFFFFFu, mxB, 1));
    mxB = fmaxf(mxB, __shfl_xor_sync(0xFFFFFFFFu, mxB, 2));

    rA0 = __expf(rA0 - mxA); rA1 = __expf(rA1 - mxA);
    rA2 = __expf(rA2 - mxA); rA3 = __expf(rA3 - mxA);
    rB0 = __expf(rB0 - mxB); rB1 = __expf(rB1 - mxB);
    rB2 = __expf(rB2 - mxB); rB3 = __expf(rB3 - mxB);

    float smA = rA0 + rA1 + rA2 + rA3;
    smA += __shfl_xor_sync(0xFFFFFFFFu, smA, 1);
    smA += __shfl_xor_sync(0xFFFFFFFFu, smA, 2);
    float smB = rB0 + rB1 + rB2 + rB3;
    smB += __shfl_xor_sync(0xFFFFFFFFu, smB, 1);
    smB += __shfl_xor_sync(0xFFFFFFFFu, smB, 2);
    const float ivA = 1.f / smA, ivB = 1.f / smB;

    // ---- pack P fragments ----
    uint32_t p[4];
    __half2 h2;
    h2 = __halves2half2(__float2half(rA0*ivA), __float2half(rA1*ivA)); p[0] = *(uint32_t*)&h2;
    h2 = __halves2half2(__float2half(rB0*ivB), __float2half(rB1*ivB)); p[1] = *(uint32_t*)&h2;
    h2 = __halves2half2(__float2half(rA2*ivA), __float2half(rA3*ivA)); p[2] = *(uint32_t*)&h2;
    h2 = __halves2half2(__float2half(rB2*ivB), __float2half(rB3*ivB)); p[3] = *(uint32_t*)&h2;

    // ---- PV; ctx into own (dead) Q smem region ----
    const uint32_t vRow = (uint32_t)(lane & 15);
    const int erow = lane >> 2;
    const int ecol = (lane & 3) * 2;
    #pragma unroll
    for (int j = 0; j < 12; j++){
        uint32_t vb[2];
        uint32_t va = sb + 2u * (vRow * ASTRIDE + (uint32_t)(1536 + h * 96 + j * 8));
        asm volatile("ldmatrix.sync.aligned.m8n8.x2.trans.shared.b16 {%0,%1},[%2];"
            : "=r"(vb[0]), "=r"(vb[1]) : "r"(va));
        float o[4] = {0,0,0,0};
        mma16816(o, p, vb[0], vb[1]);
        int c0 = h * 96 + j * 8 + ecol;
        *(__half2*)(buf + erow * ASTRIDE + c0)
            = __halves2half2(__float2half(o[0]), __float2half(o[1]));
        *(__half2*)(buf + (erow + 8) * ASTRIDE + c0)
            = __halves2half2(__float2half(o[2]), __float2half(o[3]));
    }
    __syncthreads();

    // ---- coalesced store: 16 rows x 96 uint4 (1.5KB runs) ----
    #pragma unroll
    for (int i = 0; i < 6; i++){
        int c = tid + i * 256;
        int l = c / 96, cc = c - l * 96;
        __half* dst = g_chi + ((size_t)l * SSEQ + s) * EMB + cc * 8;
        *(uint4*)dst = *(const uint4*)(buf + l * ASTRIDE + cc * 8);
    }
}

// ---------------- broadcast: out[r,:] = sum(part[r]) + b2 -------------------
__global__ __launch_bounds__(256)
void bcast(const float* __restrict__ part, const float* __restrict__ b2,
           float* __restrict__ out){
    const int r = blockIdx.x * 2 + (threadIdx.x >> 7);
    const int t = threadIdx.x & 127;
    float p = b2[0];
    #pragma unroll
    for (int s = 0; s < 12; s++) p += part[(size_t)r * 12 + s];
    float4 p4 = make_float4(p, p, p, p);
    float4* orow = (float4*)(out + (size_t)r * SSEQ);
    #pragma unroll
    for (int i = 0; i < 4; i++) orow[t + i*128] = p4;
}

// ---------------------------------------------------------------------------
extern "C" void kernel_launch(void* const* d_in, const int* in_sizes, int n_in,
                              void* d_out, int out_size){
    const float* features = (const float*)d_in[0];
    const float* in_w  = (const float*)d_in[1];
    const float* in_b  = (const float*)d_in[2];
    const float* out_w = (const float*)d_in[3];
    const float* out_b = (const float*)d_in[4];
    const float* w1    = (const float*)d_in[5];
    const float* b1    = (const float*)d_in[6];
    const float* w2    = (const float*)d_in[7];
    const float* b2    = (const float*)d_in[8];
    float* out = (float*)d_out;

    float *pt;
    __half *qkvh,*fhi,*chi,*ohi,*whi;
    cudaGetSymbolAddress((void**)&qkvh, g_qkvh);
    cudaGetSymbolAddress((void**)&pt,  g_part);
    cudaGetSymbolAddress((void**)&fhi, g_fhi);
    cudaGetSymbolAddress((void**)&chi, g_chi);
    cudaGetSymbolAddress((void**)&ohi, g_ohi);
    cudaGetSymbolAddress((void**)&whi, g_whi);

    const size_t OFF_OW = (size_t)2304*KDIM;
    const size_t OFF_W1 = (size_t)(2304+768)*KDIM;

    const int SMEM1 = 3 * 32768;
    const int SMEMA = 16 * ASTRIDE * 2;        // 73984 B
    cudaFuncSetAttribute(gemm_1p,    cudaFuncAttributeMaxDynamicSharedMemorySize, SMEM1);
    cudaFuncSetAttribute(gemm_fused, cudaFuncAttributeMaxDynamicSharedMemorySize, SMEM1);
    cudaFuncSetAttribute(attn_kernel, cudaFuncAttributeMaxDynamicSharedMemorySize, SMEMA);

    // 1-2) converts
    {
        size_t n4 = (size_t)MROWS*KDIM/4;
        conv4<<<(unsigned)((n4+255)/256), 256>>>(features, fhi, n4);
        size_t nw4 = (size_t)(2304+768+384)*KDIM/4;
        conv_w<<<(unsigned)((nw4+255)/256), 256>>>(in_w, out_w, w1, whi);
    }

    // 3) QKV = features @ in_w^T + in_b  -> fp16
    gemm_1p<<<dim3(2304/128, MROWS/128), 256, SMEM1>>>(
        fhi, whi, in_b, qkvh, 2304);

    // 4) attention (profiled slot) -> ctx fp16, coalesced writes
    attn_kernel<<<SSEQ, 256, SMEMA>>>();

    // 5) att = ctx @ out_w^T + out_b -> fp16
    gemm_1p<<<dim3(768/128, MROWS/128), 256, SMEM1>>>(
        chi, whi+OFF_OW, out_b, ohi, 768);

    // 6) fused MLP -> 12 partials/row
    gemm_fused<<<dim3(384/128, MROWS/128), 256, SMEM1>>>(
        ohi, whi+OFF_W1, b1, w2, pt);

    // 7) broadcast
    bcast<<<MROWS/2, 256>>>(pt, b2, out);
}

// round 16
// speedup vs baseline: 1.3159x; 1.0311x over previous
#include <cuda_runtime.h>
#include <cuda_fp16.h>
#include <math.h>
#include <stdint.h>

#define BBATCH 16
#define SSEQ   2048
#define EMB    768
#define NHEAD  8
#define DHEAD  96
#define MROWS  (BBATCH*SSEQ)   // 32768
#define KDIM   768
#define NCH1   12              // 768 / 64  (1-pass, BK=64)
#define ASTRIDE 2312           // attn smem row stride (halves)

// ---------------- scratch (device globals; allocation-free rule) -----------
__device__ __half  g_qkvh[(size_t)MROWS*2304];
__device__ __half  g_fhi[(size_t)MROWS*KDIM];
__device__ __half  g_chi[(size_t)MROWS*KDIM];
__device__ __half  g_ohi[(size_t)MROWS*KDIM];
__device__ float   g_part[(size_t)MROWS*12];
__device__ __half  g_whi[(size_t)(2304+768+384)*KDIM];

// ---------------- helpers ---------------------------------------------------
__device__ __forceinline__ uint32_t s2u(const void* p){
    uint32_t a;
    asm("{ .reg .u64 t; cvta.to.shared.u64 t, %1; cvt.u32.u64 %0, t; }":"=r"(a):"l"(p));
    return a;
}
#define SWZ(o)   ((o) ^ (((o) >> 3) & 0x70))
#define CP16(s, g) asm volatile("cp.async.cg.shared.global [%0], [%1], 16;"::"r"(s),"l"(g):"memory")

__device__ __forceinline__ void mma16816(float* c, const uint32_t* a, uint32_t b0, uint32_t b1){
    asm volatile("mma.sync.aligned.m16n8k16.row.col.f32.f16.f16.f32 "
        "{%0,%1,%2,%3},{%4,%5,%6,%7},{%8,%9},{%0,%1,%2,%3};"
        : "+f"(c[0]), "+f"(c[1]), "+f"(c[2]), "+f"(c[3])
        : "r"(a[0]), "r"(a[1]), "r"(a[2]), "r"(a[3]), "r"(b0), "r"(b1));
}

#define LDSM_X4(r0,r1,r2,r3,ad) \
    asm volatile("ldmatrix.sync.aligned.m8n8.x4.shared.b16 {%0,%1,%2,%3},[%4];" \
        : "=r"(r0), "=r"(r1), "=r"(r2), "=r"(r3) : "r"(ad))

// ---------------- fp32 -> fp16 converts -------------------------------------
__global__ __launch_bounds__(256)
void conv4(const float* __restrict__ src, __half* __restrict__ hi, size_t n4){
    size_t i = (size_t)blockIdx.x * blockDim.x + threadIdx.x;
    if (i >= n4) return;
    float4 v = ((const float4*)src)[i];
    ((__half2*)hi)[2*i]   = __halves2half2(__float2half(v.x), __float2half(v.y));
    ((__half2*)hi)[2*i+1] = __halves2half2(__float2half(v.z), __float2half(v.w));
}

__global__ __launch_bounds__(256)
void conv_w(const float* __restrict__ wa, const float* __restrict__ wb,
            const float* __restrict__ wc, __half* __restrict__ dst){
    const size_t n0 = (size_t)2304*KDIM/4;
    const size_t n1 = (size_t)768*KDIM/4;
    const size_t n2 = (size_t)384*KDIM/4;
    size_t i = (size_t)blockIdx.x * blockDim.x + threadIdx.x;
    if (i >= n0 + n1 + n2) return;
    const float* src; size_t off;
    if (i < n0){ src = wa; off = i; }
    else if (i < n0 + n1){ src = wb; off = i - n0; }
    else { src = wc; off = i - n0 - n1; }
    float4 v = ((const float4*)src)[off];
    ((__half2*)dst)[2*i]   = __halves2half2(__float2half(v.x), __float2half(v.y));
    ((__half2*)dst)[2*i+1] = __halves2half2(__float2half(v.z), __float2half(v.w));
}

// ---------------- pipelined mainloop body (shared by both GEMMs) -----------
// Ping-pong A/B fragment buffers; load kk+1 while MMA'ing kk.
#define GEMM_MAINLOOP(NCH)                                                      \
    uint32_t afr[2][4][4], bfr[2][8];                                           \
    auto ld_frags = [&](uint32_t sA, uint32_t sB, int kk, int buf){             \
        const uint32_t kb = (uint32_t)kk * 32u;                                 \
        LDSM_X4(bfr[buf][0], bfr[buf][1], bfr[buf][2], bfr[buf][3],             \
            sB + SWZ((uint32_t)((wn + bRow) * 128) + kb + bCol));               \
        LDSM_X4(bfr[buf][4], bfr[buf][5], bfr[buf][6], bfr[buf][7],             \
            sB + SWZ((uint32_t)((wn + 16 + bRow) * 128) + kb + bCol));          \
        _Pragma("unroll")                                                       \
        for (int mi = 0; mi < 4; mi++)                                          \
            LDSM_X4(afr[buf][mi][0], afr[buf][mi][1],                           \
                    afr[buf][mi][2], afr[buf][mi][3],                           \
                sA + SWZ((uint32_t)((wm + mi*16 + aRow) * 128) + kb + aCol));   \
    };                                                                          \
    _Pragma("unroll 1")                                                         \
    for (int t = 0; t < NCH; t++){                                              \
        if (t < NCH - 1) asm volatile("cp.async.wait_group 1;" ::: "memory");   \
        else             asm volatile("cp.async.wait_group 0;" ::: "memory");   \
        __syncthreads();                                                        \
        if (t + 2 < NCH) load_tile(t + 2);                                      \
        const uint32_t sA = sbase + (uint32_t)(t % 3) * 32768u;                 \
        const uint32_t sB = sA + 16384u;                                        \
        ld_frags(sA, sB, 0, 0);                                                 \
        _Pragma("unroll")                                                       \
        for (int kk = 0; kk < 4; kk++){                                         \
            const int cur = kk & 1, nxt = cur ^ 1;                              \
            if (kk < 3) ld_frags(sA, sB, kk + 1, nxt);                          \
            _Pragma("unroll")                                                   \
            for (int mi = 0; mi < 4; mi++)                                      \
                _Pragma("unroll")                                               \
                for (int ni = 0; ni < 4; ni++)                                  \
                    mma16816(acc[mi][ni], afr[cur][mi],                         \
                             bfr[cur][(ni>>1)*4 + (ni&1)*2],                    \
                             bfr[cur][(ni>>1)*4 + (ni&1)*2 + 1]);               \
        }                                                                       \
    }

// ---------------- 1-pass GEMM: C = A @ B^T + bias -> fp16, BK=64 -----------
__global__ __launch_bounds__(256, 2)
void gemm_1p(const __half* __restrict__ Ahi, const __half* __restrict__ Bhi,
             const float* __restrict__ bias, __half* __restrict__ Chi, int N)
{
    extern __shared__ __align__(1024) char sm[];
    constexpr uint32_t STGB = 32768u;
    const int tid = threadIdx.x, lane = tid & 31, warp = tid >> 5;
    const int m0 = blockIdx.y * 128, n0 = blockIdx.x * 128;
    const int wm = (warp & 1) * 64, wn = (warp >> 1) * 32;
    const uint32_t sbase = s2u(sm);

    auto load_tile = [&](int t){
        const uint32_t st = sbase + (uint32_t)(t % 3) * STGB;
        const int k0 = t * 64;
        #pragma unroll
        for (int i = 0; i < 4; i++){
            int g = tid + i * 256;
            int row = g >> 3, gg = g & 7;
            uint32_t d = SWZ((uint32_t)(row * 128 + gg * 16));
            CP16(st + d, Ahi + (size_t)(m0 + row) * KDIM + k0 + gg * 8);
        }
        #pragma unroll
        for (int i = 0; i < 4; i++){
            int g = tid + i * 256;
            int row = g >> 3, gg = g & 7;
            uint32_t d = SWZ((uint32_t)(row * 128 + gg * 16));
            CP16(st + 16384u + d, Bhi + (size_t)(n0 + row) * KDIM + k0 + gg * 8);
        }
        asm volatile("cp.async.commit_group;" ::: "memory");
    };

    float acc[4][4][4];
    #pragma unroll
    for (int mi = 0; mi < 4; mi++)
        #pragma unroll
        for (int ni = 0; ni < 4; ni++)
            #pragma unroll
            for (int r = 0; r < 4; r++) acc[mi][ni][r] = 0.0f;

    load_tile(0);
    load_tile(1);

    const uint32_t aRow = (uint32_t)(lane & 15);
    const uint32_t aCol = (uint32_t)(lane >> 4) * 16u;
    const uint32_t bRow = (uint32_t)(((lane >> 4) & 1) * 8 + (lane & 7));
    const uint32_t bCol = (uint32_t)((lane >> 3) & 1) * 16u;

    GEMM_MAINLOOP(NCH1)

    const int erow = lane >> 2;
    const int ecol = (lane & 3) * 2;
    #pragma unroll
    for (int mi = 0; mi < 4; mi++){
        #pragma unroll
        for (int ni = 0; ni < 4; ni++){
            const int row = m0 + wm + mi * 16 + erow;
            const int col = n0 + wn + ni * 8 + ecol;
            const float b0 = bias[col], b1 = bias[col + 1];
            float v0 = acc[mi][ni][0] + b0, v1 = acc[mi][ni][1] + b1;
            float v2 = acc[mi][ni][2] + b0, v3 = acc[mi][ni][3] + b1;
            *(__half2*)(Chi + (size_t)row * N + col)
                = __halves2half2(__float2half(v0), __float2half(v1));
            *(__half2*)(Chi + (size_t)(row + 8) * N + col)
                = __halves2half2(__float2half(v2), __float2half(v3));
        }
    }
}

// ---------------- fused MLP: 1-pass BK=64, epilogue dots w2 -----------------
__global__ __launch_bounds__(256, 2)
void gemm_fused(const __half* __restrict__ Ahi, const __half* __restrict__ Bhi,
                const float* __restrict__ bias, const float* __restrict__ w2,
                float* __restrict__ part)
{
    extern __shared__ __align__(1024) char sm[];
    constexpr uint32_t STGB = 32768u;
    const int tid = threadIdx.x, lane = tid & 31, warp = tid >> 5;
    const int m0 = blockIdx.y * 128, n0 = blockIdx.x * 128;
    const int wm = (warp & 1) * 64, wn = (warp >> 1) * 32;
    const uint32_t sbase = s2u(sm);

    auto load_tile = [&](int t){
        const uint32_t st = sbase + (uint32_t)(t % 3) * STGB;
        const int k0 = t * 64;
        #pragma unroll
        for (int i = 0; i < 4; i++){
            int g = tid + i * 256;
            int row = g >> 3, gg = g & 7;
            uint32_t d = SWZ((uint32_t)(row * 128 + gg * 16));
            CP16(st + d, Ahi + (size_t)(m0 + row) * KDIM + k0 + gg * 8);
        }
        #pragma unroll
        for (int i = 0; i < 4; i++){
            int g = tid + i * 256;
            int row = g >> 3, gg = g & 7;
            uint32_t d = SWZ((uint32_t)(row * 128 + gg * 16));
            CP16(st + 16384u + d, Bhi + (size_t)(n0 + row) * KDIM + k0 + gg * 8);
        }
        asm volatile("cp.async.commit_group;" ::: "memory");
    };

    float acc[4][4][4];
    #pragma unroll
    for (int mi = 0; mi < 4; mi++)
        #pragma unroll
        for (int ni = 0; ni < 4; ni++)
            #pragma unroll
            for (int r = 0; r < 4; r++) acc[mi][ni][r] = 0.0f;

    load_tile(0);
    load_tile(1);

    const uint32_t aRow = (uint32_t)(lane & 15);
    const uint32_t aCol = (uint32_t)(lane >> 4) * 16u;
    const uint32_t bRow = (uint32_t)(((lane >> 4) & 1) * 8 + (lane & 7));
    const uint32_t bCol = (uint32_t)((lane >> 3) & 1) * 16u;

    GEMM_MAINLOOP(NCH1)

    const int erow = lane >> 2;
    const int ecol = (lane & 3) * 2;
    const int slot = blockIdx.x * 4 + (warp >> 1);
    #pragma unroll
    for (int mi = 0; mi < 4; mi++){
        float rs0 = 0.f, rs1 = 0.f;
        #pragma unroll
        for (int ni = 0; ni < 4; ni++){
            const int col = n0 + wn + ni * 8 + ecol;
            const float b0 = bias[col], b1 = bias[col + 1];
            const float w0 = w2[col],   w1 = w2[col + 1];
            rs0 += fmaxf(acc[mi][ni][0] + b0, 0.f) * w0
                 + fmaxf(acc[mi][ni][1] + b1, 0.f) * w1;
            rs1 += fmaxf(acc[mi][ni][2] + b0, 0.f) * w0
                 + fmaxf(acc[mi][ni][3] + b1, 0.f) * w1;
        }
        rs0 += __shfl_xor_sync(0xFFFFFFFFu, rs0, 1);
        rs0 += __shfl_xor_sync(0xFFFFFFFFu, rs0, 2);
        rs1 += __shfl_xor_sync(0xFFFFFFFFu, rs1, 1);
        rs1 += __shfl_xor_sync(0xFFFFFFFFu, rs1, 2);
        if ((lane & 3) == 0){
            const int row = m0 + wm + mi * 16 + erow;
            part[(size_t)row * 12 + slot]       = rs0;
            part[(size_t)(row + 8) * 12 + slot] = rs1;
        }
    }
}

// ---------------- attention: tensor-core, smem-staged coalesced output ------
__global__ __launch_bounds__(256)
void attn_kernel(){
    extern __shared__ __align__(16) char smraw[];
    __half* buf = (__half*)smraw;                    // [16][ASTRIDE]
    const int s = blockIdx.x, tid = threadIdx.x;
    const int h = tid >> 5, lane = tid & 31;

    for (int c = tid; c < 4608; c += 256){
        int l = c / 288, cc = c - l * 288;
        const __half* src = g_qkvh + (size_t)l * ((size_t)SSEQ * 2304)
                          + (size_t)s * 2304 + cc * 8;
        *(uint4*)(buf + l * ASTRIDE + cc * 8) = *(const uint4*)src;
    }
    __syncthreads();

    const uint32_t sb = s2u(buf);
    const uint32_t qRow = (uint32_t)(lane & 15);
    const uint32_t qSel = (uint32_t)(lane >> 4) * 8u;
    const uint32_t kRow = (uint32_t)(((lane >> 4) & 1) * 8 + (lane & 7));
    const uint32_t kSel = (uint32_t)((lane >> 3) & 1) * 8u;

    float ct0[4] = {0,0,0,0}, ct1[4] = {0,0,0,0};
    #pragma unroll
    for (int kc = 0; kc < 6; kc++){
        uint32_t a[4], b[4];
        uint32_t qa = sb + 2u * (qRow * ASTRIDE + (uint32_t)(h * 96 + kc * 16) + qSel);
        LDSM_X4(a[0], a[1], a[2], a[3], qa);
        uint32_t ka = sb + 2u * (kRow * ASTRIDE + (uint32_t)(768 + h * 96 + kc * 16) + kSel);
        LDSM_X4(b[0], b[1], b[2], b[3], ka);
        mma16816(ct0, a, b[0], b[1]);
        mma16816(ct1, a, b[2], b[3]);
    }

    const float scale = rsqrtf((float)DHEAD);
    float rA0 = ct0[0]*scale, rA1 = ct0[1]*scale, rA2 = ct1[0]*scale, rA3 = ct1[1]*scale;
    float rB0 = ct0[2]*scale, rB1 = ct0[3]*scale, rB2 = ct1[2]*scale, rB3 = ct1[3]*scale;

    float mxA = fmaxf(fmaxf(rA0, rA1), fmaxf(rA2, rA3));
    mxA = fmaxf(mxA, __shfl_xor_sync(0xFFFFFFFFu, mxA, 1));
    mxA = fmaxf(mxA, __shfl_xor_sync(0xFFFFFFFFu, mxA, 2));
    float mxB = fmaxf(fmaxf(rB0, rB1), fmaxf(rB2, rB3));
    mxB = fmaxf(mxB, __shfl_xor_sync(0xFFFFFFFFu, mxB, 1));
    mxB = fmaxf(mxB, __shfl_xor_sync(0xFFFFFFFFu, mxB, 2));

    rA0 = __expf(rA0 - mxA); rA1 = __expf(rA1 - mxA);
    rA2 = __expf(rA2 - mxA); rA3 = __expf(rA3 - mxA);
    rB0 = __expf(rB0 - mxB); rB1 = __expf(rB1 - mxB);
    rB2 = __expf(rB2 - mxB); rB3 = __expf(rB3 - mxB);

    float smA = rA0 + rA1 + rA2 + rA3;
    smA += __shfl_xor_sync(0xFFFFFFFFu, smA, 1);
    smA += __shfl_xor_sync(0xFFFFFFFFu, smA, 2);
    float smB = rB0 + rB1 + rB2 + rB3;
    smB += __shfl_xor_sync(0xFFFFFFFFu, smB, 1);
    smB += __shfl_xor_sync(0xFFFFFFFFu, smB, 2);
    const float ivA = 1.f / smA, ivB = 1.f / smB;

    uint32_t p[4];
    __half2 h2;
    h2 = __halves2half2(__float2half(rA0*ivA), __float2half(rA1*ivA)); p[0] = *(uint32_t*)&h2;
    h2 = __halves2half2(__float2half(rB0*ivB), __float2half(rB1*ivB)); p[1] = *(uint32_t*)&h2;
    h2 = __halves2half2(__float2half(rA2*ivA), __float2half(rA3*ivA)); p[2] = *(uint32_t*)&h2;
    h2 = __halves2half2(__float2half(rB2*ivB), __float2half(rB3*ivB)); p[3] = *(uint32_t*)&h2;

    const uint32_t vRow = (uint32_t)(lane & 15);
    const int erow = lane >> 2;
    const int ecol = (lane & 3) * 2;
    #pragma unroll
    for (int j = 0; j < 12; j++){
        uint32_t vb[2];
        uint32_t va = sb + 2u * (vRow * ASTRIDE + (uint32_t)(1536 + h * 96 + j * 8));
        asm volatile("ldmatrix.sync.aligned.m8n8.x2.trans.shared.b16 {%0,%1},[%2];"
            : "=r"(vb[0]), "=r"(vb[1]) : "r"(va));
        float o[4] = {0,0,0,0};
        mma16816(o, p, vb[0], vb[1]);
        int c0 = h * 96 + j * 8 + ecol;
        *(__half2*)(buf + erow * ASTRIDE + c0)
            = __halves2half2(__float2half(o[0]), __float2half(o[1]));
        *(__half2*)(buf + (erow + 8) * ASTRIDE + c0)
            = __halves2half2(__float2half(o[2]), __float2half(o[3]));
    }
    __syncthreads();

    #pragma unroll
    for (int i = 0; i < 6; i++){
        int c = tid + i * 256;
        int l = c / 96, cc = c - l * 96;
        __half* dst = g_chi + ((size_t)l * SSEQ + s) * EMB + cc * 8;
        *(uint4*)dst = *(const uint4*)(buf + l * ASTRIDE + cc * 8);
    }
}

// ---------------- broadcast: out[r,:] = sum(part[r]) + b2 -------------------
__global__ __launch_bounds__(256)
void bcast(const float* __restrict__ part, const float* __restrict__ b2,
           float* __restrict__ out){
    const int r = blockIdx.x * 2 + (threadIdx.x >> 7);
    const int t = threadIdx.x & 127;
    float p = b2[0];
    #pragma unroll
    for (int s = 0; s < 12; s++) p += part[(size_t)r * 12 + s];
    float4 p4 = make_float4(p, p, p, p);
    float4* orow = (float4*)(out + (size_t)r * SSEQ);
    #pragma unroll
    for (int i = 0; i < 4; i++) orow[t + i*128] = p4;
}

// ---------------------------------------------------------------------------
extern "C" void kernel_launch(void* const* d_in, const int* in_sizes, int n_in,
                              void* d_out, int out_size){
    const float* features = (const float*)d_in[0];
    const float* in_w  = (const float*)d_in[1];
    const float* in_b  = (const float*)d_in[2];
    const float* out_w = (const float*)d_in[3];
    const float* out_b = (const float*)d_in[4];
    const float* w1    = (const float*)d_in[5];
    const float* b1    = (const float*)d_in[6];
    const float* w2    = (const float*)d_in[7];
    const float* b2    = (const float*)d_in[8];
    float* out = (float*)d_out;

    float *pt;
    __half *qkvh,*fhi,*chi,*ohi,*whi;
    cudaGetSymbolAddress((void**)&qkvh, g_qkvh);
    cudaGetSymbolAddress((void**)&pt,  g_part);
    cudaGetSymbolAddress((void**)&fhi, g_fhi);
    cudaGetSymbolAddress((void**)&chi, g_chi);
    cudaGetSymbolAddress((void**)&ohi, g_ohi);
    cudaGetSymbolAddress((void**)&whi, g_whi);

    const size_t OFF_OW = (size_t)2304*KDIM;
    const size_t OFF_W1 = (size_t)(2304+768)*KDIM;

    const int SMEM1 = 3 * 32768;
    const int SMEMA = 16 * ASTRIDE * 2;        // 73984 B
    cudaFuncSetAttribute(gemm_1p,    cudaFuncAttributeMaxDynamicSharedMemorySize, SMEM1);
    cudaFuncSetAttribute(gemm_fused, cudaFuncAttributeMaxDynamicSharedMemorySize, SMEM1);
    cudaFuncSetAttribute(attn_kernel, cudaFuncAttributeMaxDynamicSharedMemorySize, SMEMA);

    // 1-2) converts
    {
        size_t n4 = (size_t)MROWS*KDIM/4;
        conv4<<<(unsigned)((n4+255)/256), 256>>>(features, fhi, n4);
        size_t nw4 = (size_t)(2304+768+384)*KDIM/4;
        conv_w<<<(unsigned)((nw4+255)/256), 256>>>(in_w, out_w, w1, whi);
    }

    // 3) QKV = features @ in_w^T + in_b  -> fp16  (pipelined mainloop)
    gemm_1p<<<dim3(2304/128, MROWS/128), 256, SMEM1>>>(
        fhi, whi, in_b, qkvh, 2304);

    // 4) attention -> ctx fp16
    attn_kernel<<<SSEQ, 256, SMEMA>>>();

    // 5) att = ctx @ out_w^T + out_b -> fp16
    gemm_1p<<<dim3(768/128, MROWS/128), 256, SMEM1>>>(
        chi, whi+OFF_OW, out_b, ohi, 768);

    // 6) fused MLP -> 12 partials/row
    gemm_fused<<<dim3(384/128, MROWS/128), 256, SMEM1>>>(
        ohi, whi+OFF_W1, b1, w2, pt);

    // 7) broadcast
    bcast<<<MROWS/2, 256>>>(pt, b2, out);
}

// round 17
// speedup vs baseline: 1.3877x; 1.0546x over previous
#include <cuda_runtime.h>
#include <cuda_fp16.h>
#include <math.h>
#include <stdint.h>

#define BBATCH 16
#define SSEQ   2048
#define EMB    768
#define NHEAD  8
#define DHEAD  96
#define MROWS  (BBATCH*SSEQ)   // 32768
#define KDIM   768
#define NCH1   12              // 768 / 64  (1-pass, BK=64)
#define ASTRIDE 2312           // attn smem row stride (halves)

// ---------------- scratch (device globals; allocation-free rule) -----------
__device__ __half  g_qkvh[(size_t)MROWS*2304];
__device__ __half  g_fhi[(size_t)MROWS*KDIM];
__device__ __half  g_chi[(size_t)MROWS*KDIM];
__device__ __half  g_ohi[(size_t)MROWS*KDIM];
__device__ float   g_part[(size_t)MROWS*12];
__device__ __half  g_whi[(size_t)(2304+768+384)*KDIM];

// ---------------- helpers ---------------------------------------------------
__device__ __forceinline__ uint32_t s2u(const void* p){
    uint32_t a;
    asm("{ .reg .u64 t; cvta.to.shared.u64 t, %1; cvt.u32.u64 %0, t; }":"=r"(a):"l"(p));
    return a;
}
#define SWZ(o)   ((o) ^ (((o) >> 3) & 0x70))
#define CP16(s, g) asm volatile("cp.async.cg.shared.global [%0], [%1], 16;"::"r"(s),"l"(g):"memory")

__device__ __forceinline__ void mma16816(float* c, const uint32_t* a, uint32_t b0, uint32_t b1){
    asm volatile("mma.sync.aligned.m16n8k16.row.col.f32.f16.f16.f32 "
        "{%0,%1,%2,%3},{%4,%5,%6,%7},{%8,%9},{%0,%1,%2,%3};"
        : "+f"(c[0]), "+f"(c[1]), "+f"(c[2]), "+f"(c[3])
        : "r"(a[0]), "r"(a[1]), "r"(a[2]), "r"(a[3]), "r"(b0), "r"(b1));
}

#define LDSM_X4(r0,r1,r2,r3,ad) \
    asm volatile("ldmatrix.sync.aligned.m8n8.x4.shared.b16 {%0,%1,%2,%3},[%4];" \
        : "=r"(r0), "=r"(r1), "=r"(r2), "=r"(r3) : "r"(ad))

// ---------------- fp32 -> fp16 convert: features + all weights, one launch --
__global__ __launch_bounds__(256)
void conv_all(const float* __restrict__ feat, __half* __restrict__ fdst,
              const float* __restrict__ wa, const float* __restrict__ wb,
              const float* __restrict__ wc, __half* __restrict__ wdst){
    const size_t nf = (size_t)MROWS*KDIM/4;
    const size_t n0 = (size_t)2304*KDIM/4;
    const size_t n1 = (size_t)768*KDIM/4;
    const size_t n2 = (size_t)384*KDIM/4;
    size_t i = (size_t)blockIdx.x * blockDim.x + threadIdx.x;
    const float* src; __half* dst; size_t off;
    if (i < nf){ src = feat; dst = fdst; off = i; }
    else {
        size_t j = i - nf;
        if (j < n0){ src = wa; off = j; }
        else if (j < n0 + n1){ src = wb; off = j - n0; }
        else if (j < n0 + n1 + n2){ src = wc; off = j - n0 - n1; }
        else return;
        dst = wdst + (j - off) * 4;   // base offset in halves = 4*(j-off)
    }
    float4 v = ((const float4*)src)[off];
    ((__half2*)dst)[2*off]   = __halves2half2(__float2half(v.x), __float2half(v.y));
    ((__half2*)dst)[2*off+1] = __halves2half2(__float2half(v.z), __float2half(v.w));
}

// ---------------- pipelined mainloop body (shared by both GEMMs) -----------
#define GEMM_MAINLOOP(NCH)                                                      \
    uint32_t afr[2][4][4], bfr[2][8];                                           \
    auto ld_frags = [&](uint32_t sA, uint32_t sB, int kk, int buf){             \
        const uint32_t kb = (uint32_t)kk * 32u;                                 \
        LDSM_X4(bfr[buf][0], bfr[buf][1], bfr[buf][2], bfr[buf][3],             \
            sB + SWZ((uint32_t)((wn + bRow) * 128) + kb + bCol));               \
        LDSM_X4(bfr[buf][4], bfr[buf][5], bfr[buf][6], bfr[buf][7],             \
            sB + SWZ((uint32_t)((wn + 16 + bRow) * 128) + kb + bCol));          \
        _Pragma("unroll")                                                       \
        for (int mi = 0; mi < 4; mi++)                                          \
            LDSM_X4(afr[buf][mi][0], afr[buf][mi][1],                           \
                    afr[buf][mi][2], afr[buf][mi][3],                           \
                sA + SWZ((uint32_t)((wm + mi*16 + aRow) * 128) + kb + aCol));   \
    };                                                                          \
    _Pragma("unroll 1")                                                         \
    for (int t = 0; t < NCH; t++){                                              \
        if (t < NCH - 1) asm volatile("cp.async.wait_group 1;" ::: "memory");   \
        else             asm volatile("cp.async.wait_group 0;" ::: "memory");   \
        __syncthreads();                                                        \
        if (t + 2 < NCH) load_tile(t + 2);                                      \
        const uint32_t sA = sbase + (uint32_t)(t % 3) * 32768u;                 \
        const uint32_t sB = sA + 16384u;                                        \
        ld_frags(sA, sB, 0, 0);                                                 \
        _Pragma("unroll")                                                       \
        for (int kk = 0; kk < 4; kk++){                                         \
            const int cur = kk & 1, nxt = cur ^ 1;                              \
            if (kk < 3) ld_frags(sA, sB, kk + 1, nxt);                          \
            _Pragma("unroll")                                                   \
            for (int mi = 0; mi < 4; mi++)                                      \
                _Pragma("unroll")                                               \
                for (int ni = 0; ni < 4; ni++)                                  \
                    mma16816(acc[mi][ni], afr[cur][mi],                         \
                             bfr[cur][(ni>>1)*4 + (ni&1)*2],                    \
                             bfr[cur][(ni>>1)*4 + (ni&1)*2 + 1]);               \
        }                                                                       \
    }

// ---------------- 1-pass GEMM: C = A @ B^T + bias -> fp16, BK=64 -----------
__global__ __launch_bounds__(256, 2)
void gemm_1p(const __half* __restrict__ Ahi, const __half* __restrict__ Bhi,
             const float* __restrict__ bias, __half* __restrict__ Chi, int N)
{
    extern __shared__ __align__(1024) char sm[];
    constexpr uint32_t STGB = 32768u;
    const int tid = threadIdx.x, lane = tid & 31, warp = tid >> 5;
    const int m0 = blockIdx.y * 128, n0 = blockIdx.x * 128;
    const int wm = (warp & 1) * 64, wn = (warp >> 1) * 32;
    const uint32_t sbase = s2u(sm);

    auto load_tile = [&](int t){
        const uint32_t st = sbase + (uint32_t)(t % 3) * STGB;
        const int k0 = t * 64;
        #pragma unroll
        for (int i = 0; i < 4; i++){
            int g = tid + i * 256;
            int row = g >> 3, gg = g & 7;
            uint32_t d = SWZ((uint32_t)(row * 128 + gg * 16));
            CP16(st + d, Ahi + (size_t)(m0 + row) * KDIM + k0 + gg * 8);
        }
        #pragma unroll
        for (int i = 0; i < 4; i++){
            int g = tid + i * 256;
            int row = g >> 3, gg = g & 7;
            uint32_t d = SWZ((uint32_t)(row * 128 + gg * 16));
            CP16(st + 16384u + d, Bhi + (size_t)(n0 + row) * KDIM + k0 + gg * 8);
        }
        asm volatile("cp.async.commit_group;" ::: "memory");
    };

    float acc[4][4][4];
    #pragma unroll
    for (int mi = 0; mi < 4; mi++)
        #pragma unroll
        for (int ni = 0; ni < 4; ni++)
            #pragma unroll
            for (int r = 0; r < 4; r++) acc[mi][ni][r] = 0.0f;

    load_tile(0);
    load_tile(1);

    const uint32_t aRow = (uint32_t)(lane & 15);
    const uint32_t aCol = (uint32_t)(lane >> 4) * 16u;
    const uint32_t bRow = (uint32_t)(((lane >> 4) & 1) * 8 + (lane & 7));
    const uint32_t bCol = (uint32_t)((lane >> 3) & 1) * 16u;

    GEMM_MAINLOOP(NCH1)

    const int erow = lane >> 2;
    const int ecol = (lane & 3) * 2;
    #pragma unroll
    for (int mi = 0; mi < 4; mi++){
        #pragma unroll
        for (int ni = 0; ni < 4; ni++){
            const int row = m0 + wm + mi * 16 + erow;
            const int col = n0 + wn + ni * 8 + ecol;
            const float b0 = bias[col], b1 = bias[col + 1];
            float v0 = acc[mi][ni][0] + b0, v1 = acc[mi][ni][1] + b1;
            float v2 = acc[mi][ni][2] + b0, v3 = acc[mi][ni][3] + b1;
            *(__half2*)(Chi + (size_t)row * N + col)
                = __halves2half2(__float2half(v0), __float2half(v1));
            *(__half2*)(Chi + (size_t)(row + 8) * N + col)
                = __halves2half2(__float2half(v2), __float2half(v3));
        }
    }
}

// ---------------- fused MLP: 1-pass BK=64, epilogue dots w2 -----------------
__global__ __launch_bounds__(256, 2)
void gemm_fused(const __half* __restrict__ Ahi, const __half* __restrict__ Bhi,
                const float* __restrict__ bias, const float* __restrict__ w2,
                float* __restrict__ part)
{
    extern __shared__ __align__(1024) char sm[];
    constexpr uint32_t STGB = 32768u;
    const int tid = threadIdx.x, lane = tid & 31, warp = tid >> 5;
    const int m0 = blockIdx.y * 128, n0 = blockIdx.x * 128;
    const int wm = (warp & 1) * 64, wn = (warp >> 1) * 32;
    const uint32_t sbase = s2u(sm);

    auto load_tile = [&](int t){
        const uint32_t st = sbase + (uint32_t)(t % 3) * STGB;
        const int k0 = t * 64;
        #pragma unroll
        for (int i = 0; i < 4; i++){
            int g = tid + i * 256;
            int row = g >> 3, gg = g & 7;
            uint32_t d = SWZ((uint32_t)(row * 128 + gg * 16));
            CP16(st + d, Ahi + (size_t)(m0 + row) * KDIM + k0 + gg * 8);
        }
        #pragma unroll
        for (int i = 0; i < 4; i++){
            int g = tid + i * 256;
            int row = g >> 3, gg = g & 7;
            uint32_t d = SWZ((uint32_t)(row * 128 + gg * 16));
            CP16(st + 16384u + d, Bhi + (size_t)(n0 + row) * KDIM + k0 + gg * 8);
        }
        asm volatile("cp.async.commit_group;" ::: "memory");
    };

    float acc[4][4][4];
    #pragma unroll
    for (int mi = 0; mi < 4; mi++)
        #pragma unroll
        for (int ni = 0; ni < 4; ni++)
            #pragma unroll
            for (int r = 0; r < 4; r++) acc[mi][ni][r] = 0.0f;

    load_tile(0);
    load_tile(1);

    const uint32_t aRow = (uint32_t)(lane & 15);
    const uint32_t aCol = (uint32_t)(lane >> 4) * 16u;
    const uint32_t bRow = (uint32_t)(((lane >> 4) & 1) * 8 + (lane & 7));
    const uint32_t bCol = (uint32_t)((lane >> 3) & 1) * 16u;

    GEMM_MAINLOOP(NCH1)

    const int erow = lane >> 2;
    const int ecol = (lane & 3) * 2;
    const int slot = blockIdx.x * 4 + (warp >> 1);
    #pragma unroll
    for (int mi = 0; mi < 4; mi++){
        float rs0 = 0.f, rs1 = 0.f;
        #pragma unroll
        for (int ni = 0; ni < 4; ni++){
            const int col = n0 + wn + ni * 8 + ecol;
            const float b0 = bias[col], b1 = bias[col + 1];
            const float w0 = w2[col],   w1 = w2[col + 1];
            rs0 += fmaxf(acc[mi][ni][0] + b0, 0.f) * w0
                 + fmaxf(acc[mi][ni][1] + b1, 0.f) * w1;
            rs1 += fmaxf(acc[mi][ni][2] + b0, 0.f) * w0
                 + fmaxf(acc[mi][ni][3] + b1, 0.f) * w1;
        }
        rs0 += __shfl_xor_sync(0xFFFFFFFFu, rs0, 1);
        rs0 += __shfl_xor_sync(0xFFFFFFFFu, rs0, 2);
        rs1 += __shfl_xor_sync(0xFFFFFFFFu, rs1, 1);
        rs1 += __shfl_xor_sync(0xFFFFFFFFu, rs1, 2);
        if ((lane & 3) == 0){
            const int row = m0 + wm + mi * 16 + erow;
            part[(size_t)row * 12 + slot]       = rs0;
            part[(size_t)(row + 8) * 12 + slot] = rs1;
        }
    }
}

// ---------------- attention: cp.async loads, tensor-core, coalesced out -----
__global__ __launch_bounds__(256)
void attn_kernel(){
    extern __shared__ __align__(16) char smraw[];
    __half* buf = (__half*)smraw;                    // [16][ASTRIDE]
    const int s = blockIdx.x, tid = threadIdx.x;
    const int h = tid >> 5, lane = tid & 31;
    const uint32_t sb = s2u(buf);

    // async load: 4608 16B chunks, 18 per thread, all in flight
    #pragma unroll
    for (int i = 0; i < 18; i++){
        int c = tid + i * 256;
        int l = c / 288, cc = c - l * 288;
        const __half* src = g_qkvh + (size_t)l * ((size_t)SSEQ * 2304)
                          + (size_t)s * 2304 + cc * 8;
        CP16(sb + 2u * (uint32_t)(l * ASTRIDE + cc * 8), src);
    }
    asm volatile("cp.async.commit_group;" ::: "memory");
    asm volatile("cp.async.wait_group 0;" ::: "memory");
    __syncthreads();

    const uint32_t qRow = (uint32_t)(lane & 15);
    const uint32_t qSel = (uint32_t)(lane >> 4) * 8u;
    const uint32_t kRow = (uint32_t)(((lane >> 4) & 1) * 8 + (lane & 7));
    const uint32_t kSel = (uint32_t)((lane >> 3) & 1) * 8u;

    float ct0[4] = {0,0,0,0}, ct1[4] = {0,0,0,0};
    #pragma unroll
    for (int kc = 0; kc < 6; kc++){
        uint32_t a[4], b[4];
        uint32_t qa = sb + 2u * (qRow * ASTRIDE + (uint32_t)(h * 96 + kc * 16) + qSel);
        LDSM_X4(a[0], a[1], a[2], a[3], qa);
        uint32_t ka = sb + 2u * (kRow * ASTRIDE + (uint32_t)(768 + h * 96 + kc * 16) + kSel);
        LDSM_X4(b[0], b[1], b[2], b[3], ka);
        mma16816(ct0, a, b[0], b[1]);
        mma16816(ct1, a, b[2], b[3]);
    }

    const float scale = rsqrtf((float)DHEAD);
    float rA0 = ct0[0]*scale, rA1 = ct0[1]*scale, rA2 = ct1[0]*scale, rA3 = ct1[1]*scale;
    float rB0 = ct0[2]*scale, rB1 = ct0[3]*scale, rB2 = ct1[2]*scale, rB3 = ct1[3]*scale;

    float mxA = fmaxf(fmaxf(rA0, rA1), fmaxf(rA2, rA3));
    mxA = fmaxf(mxA, __shfl_xor_sync(0xFFFFFFFFu, mxA, 1));
    mxA = fmaxf(mxA, __shfl_xor_sync(0xFFFFFFFFu, mxA, 2));
    float mxB = fmaxf(fmaxf(rB0, rB1), fmaxf(rB2, rB3));
    mxB = fmaxf(mxB, __shfl_xor_sync(0xFFFFFFFFu, mxB, 1));
    mxB = fmaxf(mxB, __shfl_xor_sync(0xFFFFFFFFu, mxB, 2));

    rA0 = __expf(rA0 - mxA); rA1 = __expf(rA1 - mxA);
    rA2 = __expf(rA2 - mxA); rA3 = __expf(rA3 - mxA);
    rB0 = __expf(rB0 - mxB); rB1 = __expf(rB1 - mxB);
    rB2 = __expf(rB2 - mxB); rB3 = __expf(rB3 - mxB);

    float smA = rA0 + rA1 + rA2 + rA3;
    smA += __shfl_xor_sync(0xFFFFFFFFu, smA, 1);
    smA += __shfl_xor_sync(0xFFFFFFFFu, smA, 2);
    float smB = rB0 + rB1 + rB2 + rB3;
    smB += __shfl_xor_sync(0xFFFFFFFFu, smB, 1);
    smB += __shfl_xor_sync(0xFFFFFFFFu, smB, 2);
    const float ivA = 1.f / smA, ivB = 1.f / smB;

    uint32_t p[4];
    __half2 h2;
    h2 = __halves2half2(__float2half(rA0*ivA), __float2half(rA1*ivA)); p[0] = *(uint32_t*)&h2;
    h2 = __halves2half2(__float2half(rB0*ivB), __float2half(rB1*ivB)); p[1] = *(uint32_t*)&h2;
    h2 = __halves2half2(__float2half(rA2*ivA), __float2half(rA3*ivA)); p[2] = *(uint32_t*)&h2;
    h2 = __halves2half2(__float2half(rB2*ivB), __float2half(rB3*ivB)); p[3] = *(uint32_t*)&h2;

    const uint32_t vRow = (uint32_t)(lane & 15);
    const int erow = lane >> 2;
    const int ecol = (lane & 3) * 2;
    #pragma unroll
    for (int j = 0; j < 12; j++){
        uint32_t vb[2];
        uint32_t va = sb + 2u * (vRow * ASTRIDE + (uint32_t)(1536 + h * 96 + j * 8));
        asm volatile("ldmatrix.sync.aligned.m8n8.x2.trans.shared.b16 {%0,%1},[%2];"
            : "=r"(vb[0]), "=r"(vb[1]) : "r"(va));
        float o[4] = {0,0,0,0};
        mma16816(o, p, vb[0], vb[1]);
        int c0 = h * 96 + j * 8 + ecol;
        *(__half2*)(buf + erow * ASTRIDE + c0)
            = __halves2half2(__float2half(o[0]), __float2half(o[1]));
        *(__half2*)(buf + (erow + 8) * ASTRIDE + c0)
            = __halves2half2(__float2half(o[2]), __float2half(o[3]));
    }
    __syncthreads();

    #pragma unroll
    for (int i = 0; i < 6; i++){
        int c = tid + i * 256;
        int l = c / 96, cc = c - l * 96;
        __half* dst = g_chi + ((size_t)l * SSEQ + s) * EMB + cc * 8;
        *(uint4*)dst = *(const uint4*)(buf + l * ASTRIDE + cc * 8);
    }
}

// ---------------- broadcast: out[r,:] = sum(part[r]) + b2 -------------------
__global__ __launch_bounds__(256)
void bcast(const float* __restrict__ part, const float* __restrict__ b2,
           float* __restrict__ out){
    const int r = blockIdx.x * 2 + (threadIdx.x >> 7);
    const int t = threadIdx.x & 127;
    float p = b2[0];
    #pragma unroll
    for (int s = 0; s < 12; s++) p += part[(size_t)r * 12 + s];
    float4 p4 = make_float4(p, p, p, p);
    float4* orow = (float4*)(out + (size_t)r * SSEQ);
    #pragma unroll
    for (int i = 0; i < 4; i++) orow[t + i*128] = p4;
}

// ---------------------------------------------------------------------------
extern "C" void kernel_launch(void* const* d_in, const int* in_sizes, int n_in,
                              void* d_out, int out_size){
    const float* features = (const float*)d_in[0];
    const float* in_w  = (const float*)d_in[1];
    const float* in_b  = (const float*)d_in[2];
    const float* out_w = (const float*)d_in[3];
    const float* out_b = (const float*)d_in[4];
    const float* w1    = (const float*)d_in[5];
    const float* b1    = (const float*)d_in[6];
    const float* w2    = (const float*)d_in[7];
    const float* b2    = (const float*)d_in[8];
    float* out = (float*)d_out;

    float *pt;
    __half *qkvh,*fhi,*chi,*ohi,*whi;
    cudaGetSymbolAddress((void**)&qkvh, g_qkvh);
    cudaGetSymbolAddress((void**)&pt,  g_part);
    cudaGetSymbolAddress((void**)&fhi, g_fhi);
    cudaGetSymbolAddress((void**)&chi, g_chi);
    cudaGetSymbolAddress((void**)&ohi, g_ohi);
    cudaGetSymbolAddress((void**)&whi, g_whi);

    const size_t OFF_OW = (size_t)2304*KDIM;
    const size_t OFF_W1 = (size_t)(2304+768)*KDIM;

    const int SMEM1 = 3 * 32768;
    const int SMEMA = 16 * ASTRIDE * 2;        // 73984 B
    cudaFuncSetAttribute(gemm_1p,    cudaFuncAttributeMaxDynamicSharedMemorySize, SMEM1);
    cudaFuncSetAttribute(gemm_fused, cudaFuncAttributeMaxDynamicSharedMemorySize, SMEM1);
    cudaFuncSetAttribute(attn_kernel, cudaFuncAttributeMaxDynamicSharedMemorySize, SMEMA);

    // 1) one convert launch: features + all weights
    {
        size_t nt = (size_t)MROWS*KDIM/4 + (size_t)(2304+768+384)*KDIM/4;
        conv_all<<<(unsigned)((nt+255)/256), 256>>>(
            features, fhi, in_w, out_w, w1, whi);
    }

    // 2) QKV = features @ in_w^T + in_b  -> fp16
    gemm_1p<<<dim3(2304/128, MROWS/128), 256, SMEM1>>>(
        fhi, whi, in_b, qkvh, 2304);

    // 3) attention -> ctx fp16 (cp.async loads)
    attn_kernel<<<SSEQ, 256, SMEMA>>>();

    // 4) att = ctx @ out_w^T + out_b -> fp16
    gemm_1p<<<dim3(768/128, MROWS/128), 256, SMEM1>>>(
        chi, whi+OFF_OW, out_b, ohi, 768);

    // 5) fused MLP -> 12 partials/row
    gemm_fused<<<dim3(384/128, MROWS/128), 256, SMEM1>>>(
        ohi, whi+OFF_W1, b1, w2, pt);

    // 6) broadcast
    bcast<<<MROWS/2, 256>>>(pt, b2, out);
}